// round 5
// baseline (speedup 1.0000x reference)
#include <cuda_runtime.h>
#include <cuda_bf16.h>
#include <math_constants.h>
#include <cstdint>

#define D_IN   2048
#define D_OUT  2048
#define HD     128
#define NG     4
#define HPG    4
#define SEQ    2048
#define KVD    1024   /* fused K|V buffer width */

// ---------------- scratch (no cudaMalloc allowed) ----------------
__device__ float g_X [4096 * 2048];   // x, tf32-rounded
__device__ float g_Wq[2048 * 2048];
__device__ float g_Wk[2048 * 512];
__device__ float g_Wv[2048 * 512];
__device__ float g_Wo[2048 * 2048];
__device__ float g_Q [4096 * 2048];   // q proj, scaled + tf32
__device__ float g_KV[4096 * 1024];   // [K | V], tf32
__device__ float g_C [4096 * 2048];   // ctx, tf32

// ---------------- helpers ----------------
__device__ __forceinline__ uint32_t f2tf(float x) {
    uint32_t u;
    asm("cvt.rna.tf32.f32 %0, %1;" : "=r"(u) : "f"(x));
    return u;
}
__device__ __forceinline__ float tf32r(float x) { return __uint_as_float(f2tf(x)); }

__device__ __forceinline__ void mma_tf32(float* d, const uint32_t* a, const uint32_t* b) {
    asm volatile(
        "mma.sync.aligned.m16n8k8.row.col.f32.tf32.tf32.f32 "
        "{%0,%1,%2,%3}, {%4,%5,%6,%7}, {%8,%9}, {%0,%1,%2,%3};"
        : "+f"(d[0]), "+f"(d[1]), "+f"(d[2]), "+f"(d[3])
        : "r"(a[0]), "r"(a[1]), "r"(a[2]), "r"(a[3]), "r"(b[0]), "r"(b[1]));
}
__device__ __forceinline__ uint32_t smem_u32(const void* p) {
    uint32_t a;
    asm("{ .reg .u64 t; cvta.to.shared.u64 t, %1; cvt.u32.u64 %0, t; }" : "=r"(a) : "l"(p));
    return a;
}
#define CP_ASYNC16(dst, src) \
    asm volatile("cp.async.cg.shared.global [%0], [%1], 16;" :: "r"(dst), "l"(src) : "memory")
#define CP_COMMIT() asm volatile("cp.async.commit_group;" ::: "memory")
#define CP_WAIT0()  asm volatile("cp.async.wait_group 0;" ::: "memory")
#define CP_WAIT1()  asm volatile("cp.async.wait_group 1;" ::: "memory")

#define SCALE 0.08838834764831845f   /* 1/sqrt(128) */

// ---------------- prepass: tf32 rounding ----------------
__global__ void round_tf32(const float* __restrict__ in, float* __restrict__ out) {
    size_t i = ((size_t)blockIdx.x * blockDim.x + threadIdx.x) * 4;
    float4 v = *(const float4*)(in + i);
    v.x = tf32r(v.x); v.y = tf32r(v.y); v.z = tf32r(v.z); v.w = tf32r(v.w);
    *(float4*)(out + i) = v;
}

// ---------------- tf32 mma GEMM: CTA 128x256, 8 warps @ 64x64 ----------------
#define GBK 32
#define ALD 36
#define BLD 264
#define AS_F (128 * ALD)
#define BS_F (GBK * BLD)
#define STG_F (AS_F + BS_F)
#define GEMM_SMEM (3 * STG_F * 4)

template <bool PROJ>
__global__ __launch_bounds__(256, 1) void gemm_k(
    const float* __restrict__ A,
    const float* __restrict__ B0, const float* __restrict__ B1, const float* __restrict__ B2,
    float* __restrict__ C0, float* __restrict__ C1,
    const float* __restrict__ bias, int M, int K)
{
    extern __shared__ float smg[];
    const int tid = threadIdx.x;
    const int wid = tid >> 5, l = tid & 31;
    const int lq = l >> 2, lr = l & 3;
    const int m0 = blockIdx.y * 128;
    const int n0 = blockIdx.x * 256;
    const int wm = (wid & 1) * 64, wn = (wid >> 1) * 64;
    const uint32_t smb = smem_u32(smg);

    const float* Bp; int ldB; float* Cp; int ldC; bool doscale = false;
    if (PROJ) {
        if (n0 < 2048)      { Bp = B0 + n0;          ldB = 2048; Cp = C0 + n0;                ldC = 2048; doscale = true; }
        else if (n0 < 2560) { Bp = B1 + (n0 - 2048); ldB = 512;  Cp = C1 + (n0 - 2048);       ldC = 1024; }
        else                { Bp = B2 + (n0 - 2560); ldB = 512;  Cp = C1 + (n0 - 2560 + 512); ldC = 1024; }
    } else { Bp = B0 + n0; ldB = 2048; Cp = C0 + n0; ldC = 2048; }

    const int kiters = K / GBK;

    float acc[4][8][4];
#pragma unroll
    for (int i = 0; i < 4; i++)
#pragma unroll
        for (int j = 0; j < 8; j++)
#pragma unroll
            for (int r = 0; r < 4; r++) acc[i][j][r] = 0.f;

    uint32_t af[2][4][4], bf[2][8][2];

#define G_LOAD(s, kc) do {                                                        \
        uint32_t _ab = smb + (s) * (STG_F * 4);                                   \
        uint32_t _bb = _ab + AS_F * 4;                                            \
        _Pragma("unroll")                                                         \
        for (int _i = 0; _i < 4; _i++) {                                          \
            int _e = tid + _i * 256, _r = _e >> 3, _kq = _e & 7;                  \
            CP_ASYNC16(_ab + (_r * ALD + _kq * 4) * 4,                            \
                (const void*)(A + (size_t)(m0 + _r) * K + (kc) * GBK + _kq * 4)); \
        }                                                                         \
        _Pragma("unroll")                                                         \
        for (int _i = 0; _i < 8; _i++) {                                          \
            int _e = tid + _i * 256, _r = _e >> 6, _cq = _e & 63;                 \
            CP_ASYNC16(_bb + (_r * BLD + _cq * 4) * 4,                            \
                (const void*)(Bp + (size_t)((kc) * GBK + _r) * ldB + _cq * 4));   \
        }                                                                         \
    } while (0)

#define LD_FRAGS(bank, k8) do {                                                   \
        _Pragma("unroll")                                                         \
        for (int _mf = 0; _mf < 4; _mf++) {                                       \
            const float* _p = As + (wm + _mf * 16 + lq) * ALD + (k8) + lr;        \
            af[bank][_mf][0] = __float_as_uint(_p[0]);                            \
            af[bank][_mf][1] = __float_as_uint(_p[8 * ALD]);                      \
            af[bank][_mf][2] = __float_as_uint(_p[4]);                            \
            af[bank][_mf][3] = __float_as_uint(_p[8 * ALD + 4]);                  \
        }                                                                         \
        _Pragma("unroll")                                                         \
        for (int _nf = 0; _nf < 8; _nf++) {                                       \
            const float* _p = Bs + ((k8) + lr) * BLD + wn + _nf * 8 + lq;         \
            bf[bank][_nf][0] = __float_as_uint(_p[0]);                            \
            bf[bank][_nf][1] = __float_as_uint(_p[4 * BLD]);                      \
        }                                                                         \
    } while (0)

    G_LOAD(0, 0); CP_COMMIT();
    G_LOAD(1, 1); CP_COMMIT();

    for (int it = 0; it < kiters; it++) {
        CP_WAIT1();
        __syncthreads();
        if (it + 2 < kiters) G_LOAD((it + 2) % 3, it + 2);
        CP_COMMIT();

        const float* As = smg + (it % 3) * STG_F;
        const float* Bs = As + AS_F;

        LD_FRAGS(0, 0);
#pragma unroll
        for (int ks = 0; ks < 4; ks++) {
            if (ks < 3) LD_FRAGS((ks + 1) & 1, (ks + 1) * 8);
            const int cb = ks & 1;
#pragma unroll
            for (int mf = 0; mf < 4; mf++)
#pragma unroll
                for (int nf = 0; nf < 8; nf++)
                    mma_tf32(acc[mf][nf], af[cb][mf], bf[cb][nf]);
        }
        __syncthreads();
    }

    // epilogue
#pragma unroll
    for (int mf = 0; mf < 4; mf++) {
        const int row = m0 + wm + mf * 16 + lq;
#pragma unroll
        for (int nf = 0; nf < 8; nf++) {
            const int col = wn + nf * 8 + 2 * lr;
            float v0 = acc[mf][nf][0], v1 = acc[mf][nf][1];
            float v2 = acc[mf][nf][2], v3 = acc[mf][nf][3];
            if (PROJ) {
                if (doscale) { v0 *= SCALE; v1 *= SCALE; v2 *= SCALE; v3 *= SCALE; }
                v0 = tf32r(v0); v1 = tf32r(v1); v2 = tf32r(v2); v3 = tf32r(v3);
            } else {
                float2 b = *(const float2*)(bias + n0 + col);
                v0 += b.x; v1 += b.y; v2 += b.x; v3 += b.y;
            }
            *(float2*)(Cp + (size_t)row * ldC + col)       = make_float2(v0, v1);
            *(float2*)(Cp + (size_t)(row + 8) * ldC + col) = make_float2(v2, v3);
        }
    }
#undef G_LOAD
#undef LD_FRAGS
}

// ---------------- tf32 mma flash-attention ----------------
// 128 threads (4 warps). CTA: (batch, head) x 128 q-rows; warp: 32 rows (2 mf).
// Q in smem (read once per tile); K/V double-buffered cp.async;
// P never touches smem: c-frag -> a-frag via shuffle transpose.
#define QROW 132
#define KROW 132
#define VROW 136
#define QS_F (128 * QROW)                     /* 16896 */
#define KS_ST (64 * KROW)                     /* 8448 */
#define VS_ST (64 * VROW)                     /* 8704 */
#define ATTN_SMEM ((QS_F + 2 * KS_ST + 2 * VS_ST) * 4)   /* 204800 B */

__global__ __launch_bounds__(128, 1) void attn_mma(
    const float* __restrict__ Q, const float* __restrict__ KV,
    float* __restrict__ C)
{
    extern __shared__ float sm[];
    float* Qs = sm;
    const int tid = threadIdx.x;
    const int wid = tid >> 5, l = tid & 31;
    const int lq = l >> 2, lr = l & 3;
    const int wq = wid * 32;

    const int qc = gridDim.x - 1 - blockIdx.x;   // long CTAs first
    const int hh = blockIdx.y;
    const int bi = hh >> 4;
    const int gi = (hh >> 2) & 3;
    const int hi = hh & 3;
    const int qcol = (gi * HPG + hi) * HD;
    const int kcolK = gi * HD;
    const int kcolV = 512 + gi * HD;
    const size_t rowbase = (size_t)bi * SEQ;
    const int qbase = qc * 128;
    const uint32_t smb = smem_u32(sm);

    // ---- load Q tile [128 x 128] into smem ----
    for (int i = tid; i < 128 * 32; i += 128) {
        int r = i >> 5, c4 = (i & 31) << 2;
        *(float4*)&Qs[r * QROW + c4] =
            *(const float4*)(Q + (rowbase + qbase + r) * (size_t)D_OUT + qcol + c4);
    }

    float o[2][16][4];
#pragma unroll
    for (int mf = 0; mf < 2; mf++)
#pragma unroll
        for (int i = 0; i < 16; i++)
#pragma unroll
            for (int r = 0; r < 4; r++) o[mf][i][r] = 0.f;
    float mm[2][2], ll[2][2];
#pragma unroll
    for (int mf = 0; mf < 2; mf++) {
        mm[mf][0] = -CUDART_INF_F; mm[mf][1] = -CUDART_INF_F;
        ll[mf][0] = 0.f; ll[mf][1] = 0.f;
    }

    const int jmax = 2 * qc + 1;

#define KV_LOAD(ss, jj) do {                                                     \
        uint32_t _kb = smb + (QS_F + (ss) * KS_ST) * 4;                          \
        uint32_t _vb = smb + (QS_F + 2 * KS_ST + (ss) * VS_ST) * 4;              \
        const float* _gk = KV + (rowbase + (jj) * 64) * KVD + kcolK;             \
        const float* _gv = KV + (rowbase + (jj) * 64) * KVD + kcolV;             \
        _Pragma("unroll")                                                        \
        for (int _u = 0; _u < 16; _u++) {                                        \
            int _e = tid + _u * 128, _r = _e >> 5, _c4 = (_e & 31) << 2;         \
            CP_ASYNC16(_kb + (_r * KROW + _c4) * 4,                              \
                       (const void*)(_gk + (size_t)_r * KVD + _c4));             \
            CP_ASYNC16(_vb + (_r * VROW + _c4) * 4,                              \
                       (const void*)(_gv + (size_t)_r * KVD + _c4));             \
        }                                                                        \
    } while (0)

    KV_LOAD(0, 0); CP_COMMIT();

    for (int j = 0; j <= jmax; j++) {
        CP_WAIT0();
        __syncthreads();   // KV stage ready; also covers Q visibility on j=0
        if (j < jmax) KV_LOAD((j + 1) & 1, j + 1);
        CP_COMMIT();

        const int st = j & 1;
        const float* Ks = sm + QS_F + st * KS_ST;
        const float* Vs = sm + QS_F + 2 * KS_ST + st * VS_ST;
        const int kbase = j * 64;
        if (kbase > qbase + wq + 31) continue;   // warp fully masked

        // ---- S = Q @ K^T : 32 q-rows x 64 keys ----
        float s_[2][8][4];
#pragma unroll
        for (int mf = 0; mf < 2; mf++)
#pragma unroll
            for (int nf = 0; nf < 8; nf++)
#pragma unroll
                for (int r = 0; r < 4; r++) s_[mf][nf][r] = 0.f;

#pragma unroll
        for (int kf = 0; kf < 16; kf++) {
            uint32_t qa[2][4];
#pragma unroll
            for (int mf = 0; mf < 2; mf++) {
                const float* qp = Qs + (wq + mf * 16 + lq) * QROW + kf * 8 + lr;
                qa[mf][0] = __float_as_uint(qp[0]);
                qa[mf][1] = __float_as_uint(qp[8 * QROW]);
                qa[mf][2] = __float_as_uint(qp[4]);
                qa[mf][3] = __float_as_uint(qp[8 * QROW + 4]);
            }
#pragma unroll
            for (int nf = 0; nf < 8; nf++) {
                const float* kp = Ks + (nf * 8 + lq) * KROW + kf * 8 + lr;
                uint32_t b[2] = { __float_as_uint(kp[0]), __float_as_uint(kp[4]) };
                mma_tf32(s_[0][nf], qa[0], b);
                mma_tf32(s_[1][nf], qa[1], b);
            }
        }

        // ---- softmax (per mf) ----
        const bool needmask = (kbase + 63 > qbase + wq);
#pragma unroll
        for (int mf = 0; mf < 2; mf++) {
            const int gr0 = qbase + wq + mf * 16 + lq;
            const int gr1 = gr0 + 8;
            float mx0 = -CUDART_INF_F, mx1 = -CUDART_INF_F;
#pragma unroll
            for (int nf = 0; nf < 8; nf++) {
                if (needmask) {
                    const int c0 = kbase + nf * 8 + 2 * lr;
                    if (c0 > gr0)     s_[mf][nf][0] = -CUDART_INF_F;
                    if (c0 + 1 > gr0) s_[mf][nf][1] = -CUDART_INF_F;
                    if (c0 > gr1)     s_[mf][nf][2] = -CUDART_INF_F;
                    if (c0 + 1 > gr1) s_[mf][nf][3] = -CUDART_INF_F;
                }
                mx0 = fmaxf(mx0, fmaxf(s_[mf][nf][0], s_[mf][nf][1]));
                mx1 = fmaxf(mx1, fmaxf(s_[mf][nf][2], s_[mf][nf][3]));
            }
#pragma unroll
            for (int msk = 1; msk < 4; msk <<= 1) {
                mx0 = fmaxf(mx0, __shfl_xor_sync(0xffffffffu, mx0, msk));
                mx1 = fmaxf(mx1, __shfl_xor_sync(0xffffffffu, mx1, msk));
            }
            const float nm0 = fmaxf(mm[mf][0], mx0);
            const float nm1 = fmaxf(mm[mf][1], mx1);
            const float al0 = __expf(mm[mf][0] - nm0);
            const float al1 = __expf(mm[mf][1] - nm1);
            mm[mf][0] = nm0; mm[mf][1] = nm1;

            float sm0 = 0.f, sm1 = 0.f;
#pragma unroll
            for (int nf = 0; nf < 8; nf++) {
                float p0 = tf32r(__expf(s_[mf][nf][0] - nm0));
                float p1 = tf32r(__expf(s_[mf][nf][1] - nm0));
                float p2 = tf32r(__expf(s_[mf][nf][2] - nm1));
                float p3 = tf32r(__expf(s_[mf][nf][3] - nm1));
                s_[mf][nf][0] = p0; s_[mf][nf][1] = p1;
                s_[mf][nf][2] = p2; s_[mf][nf][3] = p3;
                sm0 += p0 + p1; sm1 += p2 + p3;
            }
#pragma unroll
            for (int msk = 1; msk < 4; msk <<= 1) {
                sm0 += __shfl_xor_sync(0xffffffffu, sm0, msk);
                sm1 += __shfl_xor_sync(0xffffffffu, sm1, msk);
            }
            ll[mf][0] = ll[mf][0] * al0 + sm0;
            ll[mf][1] = ll[mf][1] * al1 + sm1;
#pragma unroll
            for (int nf = 0; nf < 16; nf++) {
                o[mf][nf][0] *= al0; o[mf][nf][1] *= al0;
                o[mf][nf][2] *= al1; o[mf][nf][3] *= al1;
            }
        }

        // ---- O += P @ V : P a-frags via shuffle transpose of s_ ----
        const int src0 = (lq << 2) + (lr >> 1);
        const int src1 = src0 + 2;
        const bool odd = (lr & 1);
#pragma unroll
        for (int kf = 0; kf < 8; kf++) {
            uint32_t aP[2][4];
#pragma unroll
            for (int mf = 0; mf < 2; mf++) {
                float t00 = __shfl_sync(0xffffffffu, s_[mf][kf][0], src0);
                float t01 = __shfl_sync(0xffffffffu, s_[mf][kf][1], src0);
                float t20 = __shfl_sync(0xffffffffu, s_[mf][kf][2], src0);
                float t21 = __shfl_sync(0xffffffffu, s_[mf][kf][3], src0);
                float t40 = __shfl_sync(0xffffffffu, s_[mf][kf][0], src1);
                float t41 = __shfl_sync(0xffffffffu, s_[mf][kf][1], src1);
                float t60 = __shfl_sync(0xffffffffu, s_[mf][kf][2], src1);
                float t61 = __shfl_sync(0xffffffffu, s_[mf][kf][3], src1);
                aP[mf][0] = __float_as_uint(odd ? t01 : t00);
                aP[mf][1] = __float_as_uint(odd ? t21 : t20);
                aP[mf][2] = __float_as_uint(odd ? t41 : t40);
                aP[mf][3] = __float_as_uint(odd ? t61 : t60);
            }
#pragma unroll
            for (int nf = 0; nf < 16; nf++) {
                const float* vp = Vs + (kf * 8 + lr) * VROW + nf * 8 + lq;
                uint32_t b[2] = { __float_as_uint(vp[0]),
                                  __float_as_uint(vp[4 * VROW]) };
                mma_tf32(o[0][nf], aP[0], b);
                mma_tf32(o[1][nf], aP[1], b);
            }
        }
    }

    // ---- epilogue: normalize + tf32-round (feeds O-proj) ----
#pragma unroll
    for (int mf = 0; mf < 2; mf++) {
        const float inv0 = 1.f / ll[mf][0], inv1 = 1.f / ll[mf][1];
        const size_t r0 = rowbase + qbase + wq + mf * 16 + lq;
        const size_t r1 = r0 + 8;
#pragma unroll
        for (int nf = 0; nf < 16; nf++) {
            const int col = qcol + nf * 8 + 2 * lr;
            *(float2*)(C + r0 * D_OUT + col) =
                make_float2(tf32r(o[mf][nf][0] * inv0), tf32r(o[mf][nf][1] * inv0));
            *(float2*)(C + r1 * D_OUT + col) =
                make_float2(tf32r(o[mf][nf][2] * inv1), tf32r(o[mf][nf][3] * inv1));
        }
    }
#undef KV_LOAD
}

// ---------------------------------------------------------------------------
extern "C" void kernel_launch(void* const* d_in, const int* in_sizes, int n_in,
                              void* d_out, int out_size)
{
    const float* x  = (const float*)d_in[0];
    const float* Wq = (const float*)d_in[1];
    const float* Wk = (const float*)d_in[2];
    const float* Wv = (const float*)d_in[3];
    const float* Wo = (const float*)d_in[4];
    const float* bo = (const float*)d_in[5];

    const int M = in_sizes[0] / D_IN;   // 4096
    const int B = M / SEQ;              // 2

    float *Xr, *Wqr, *Wkr, *Wvr, *Wor, *Qp, *KVp, *Cp;
    cudaGetSymbolAddress((void**)&Xr,  g_X);
    cudaGetSymbolAddress((void**)&Wqr, g_Wq);
    cudaGetSymbolAddress((void**)&Wkr, g_Wk);
    cudaGetSymbolAddress((void**)&Wvr, g_Wv);
    cudaGetSymbolAddress((void**)&Wor, g_Wo);
    cudaGetSymbolAddress((void**)&Qp,  g_Q);
    cudaGetSymbolAddress((void**)&KVp, g_KV);
    cudaGetSymbolAddress((void**)&Cp,  g_C);

    cudaFuncSetAttribute(gemm_k<true>,
                         cudaFuncAttributeMaxDynamicSharedMemorySize, GEMM_SMEM);
    cudaFuncSetAttribute(gemm_k<false>,
                         cudaFuncAttributeMaxDynamicSharedMemorySize, GEMM_SMEM);
    cudaFuncSetAttribute(attn_mma,
                         cudaFuncAttributeMaxDynamicSharedMemorySize, ATTN_SMEM);

    // prepass: tf32-round x and weights
    round_tf32<<<(M * D_IN) / 1024, 256>>>(x, Xr);
    round_tf32<<<(D_IN * D_OUT) / 1024, 256>>>(Wq, Wqr);
    round_tf32<<<(D_IN * 512) / 1024, 256>>>(Wk, Wkr);
    round_tf32<<<(D_IN * 512) / 1024, 256>>>(Wv, Wvr);
    round_tf32<<<(D_OUT * D_OUT) / 1024, 256>>>(Wo, Wor);

    // fused QKV projection: N = 2048 (Q) + 512 (K) + 512 (V) = 3072
    gemm_k<true><<<dim3(12, M / 128), 256, GEMM_SMEM>>>(
        Xr, Wqr, Wkr, Wvr, Qp, KVp, nullptr, M, D_IN);

    attn_mma<<<dim3(SEQ / 128, B * 16), 128, ATTN_SMEM>>>(Qp, KVp, Cp);

    // output projection + bias
    gemm_k<false><<<dim3(8, M / 128), 256, GEMM_SMEM>>>(
        Cp, Wor, nullptr, nullptr, (float*)d_out, nullptr, bo, M, D_OUT);
}

// round 6
// speedup vs baseline: 1.1864x; 1.1864x over previous
#include <cuda_runtime.h>
#include <cuda_bf16.h>
#include <math_constants.h>
#include <cstdint>

#define D_IN   2048
#define D_OUT  2048
#define HD     128
#define NG     4
#define HPG    4
#define SEQ    2048
#define KVD    1024   /* fused K|V buffer width */

// ---------------- scratch (no cudaMalloc allowed) ----------------
__device__ float g_X [4096 * 2048];   // x, tf32-rounded
__device__ float g_Wq[2048 * 2048];
__device__ float g_Wk[2048 * 512];
__device__ float g_Wv[2048 * 512];
__device__ float g_Wo[2048 * 2048];
__device__ float g_Q [4096 * 2048];   // q proj, scaled + tf32
__device__ float g_KV[4096 * 1024];   // [K | V], tf32
__device__ float g_C [4096 * 2048];   // ctx, tf32

// ---------------- helpers ----------------
__device__ __forceinline__ uint32_t f2tf(float x) {
    uint32_t u;
    asm("cvt.rna.tf32.f32 %0, %1;" : "=r"(u) : "f"(x));
    return u;
}
__device__ __forceinline__ float tf32r(float x) { return __uint_as_float(f2tf(x)); }

__device__ __forceinline__ void mma_tf32(float* d, const uint32_t* a, const uint32_t* b) {
    asm volatile(
        "mma.sync.aligned.m16n8k8.row.col.f32.tf32.tf32.f32 "
        "{%0,%1,%2,%3}, {%4,%5,%6,%7}, {%8,%9}, {%0,%1,%2,%3};"
        : "+f"(d[0]), "+f"(d[1]), "+f"(d[2]), "+f"(d[3])
        : "r"(a[0]), "r"(a[1]), "r"(a[2]), "r"(a[3]), "r"(b[0]), "r"(b[1]));
}
__device__ __forceinline__ uint32_t smem_u32(const void* p) {
    uint32_t a;
    asm("{ .reg .u64 t; cvta.to.shared.u64 t, %1; cvt.u32.u64 %0, t; }" : "=r"(a) : "l"(p));
    return a;
}
#define CP_ASYNC16(dst, src) \
    asm volatile("cp.async.cg.shared.global [%0], [%1], 16;" :: "r"(dst), "l"(src) : "memory")
#define CP_COMMIT() asm volatile("cp.async.commit_group;" ::: "memory")
#define CP_WAIT0()  asm volatile("cp.async.wait_group 0;" ::: "memory")
#define CP_WAIT1()  asm volatile("cp.async.wait_group 1;" ::: "memory")

#define SCALE 0.08838834764831845f   /* 1/sqrt(128) */

// ---------------- prepass: fused tf32 rounding of x + all weights ----------------
__global__ void round_all(const float* __restrict__ x,  float* __restrict__ xr,
                          const float* __restrict__ wq, float* __restrict__ wqr,
                          const float* __restrict__ wk, float* __restrict__ wkr,
                          const float* __restrict__ wv, float* __restrict__ wvr,
                          const float* __restrict__ wo, float* __restrict__ wor,
                          int Mtot)
{
    const size_t n_x = (size_t)Mtot * D_IN / 4;
    const size_t n_q = (size_t)D_IN * D_OUT / 4;
    const size_t n_k = (size_t)D_IN * 512 / 4;
    const size_t stride = (size_t)gridDim.x * blockDim.x;
    const size_t i0 = (size_t)blockIdx.x * blockDim.x + threadIdx.x;

    const float4* src[5] = { (const float4*)x, (const float4*)wq, (const float4*)wk,
                             (const float4*)wv, (const float4*)wo };
    float4* dst[5] = { (float4*)xr, (float4*)wqr, (float4*)wkr, (float4*)wvr, (float4*)wor };
    const size_t cnt[5] = { n_x, n_q, n_k, n_k, n_q };

#pragma unroll
    for (int s = 0; s < 5; s++) {
        for (size_t i = i0; i < cnt[s]; i += stride) {
            float4 v = src[s][i];
            v.x = tf32r(v.x); v.y = tf32r(v.y); v.z = tf32r(v.z); v.w = tf32r(v.w);
            dst[s][i] = v;
        }
    }
}

// ---------------- tf32 mma GEMM: CTA 128x256, 8 warps @ 64x64 (R4) -------------
#define GBK 32
#define ALD 36
#define BLD 264
#define AS_F (128 * ALD)
#define BS_F (GBK * BLD)
#define STG_F (AS_F + BS_F)
#define GEMM_SMEM (3 * STG_F * 4)

template <bool PROJ>
__global__ __launch_bounds__(256, 1) void gemm_k(
    const float* __restrict__ A,
    const float* __restrict__ B0, const float* __restrict__ B1, const float* __restrict__ B2,
    float* __restrict__ C0, float* __restrict__ C1,
    const float* __restrict__ bias, int M, int K)
{
    extern __shared__ float smg[];
    const int tid = threadIdx.x;
    const int wid = tid >> 5, l = tid & 31;
    const int lq = l >> 2, lr = l & 3;
    const int m0 = blockIdx.y * 128;
    const int n0 = blockIdx.x * 256;
    const int wm = (wid & 1) * 64, wn = (wid >> 1) * 64;
    const uint32_t smb = smem_u32(smg);

    const float* Bp; int ldB; float* Cp; int ldC; bool doscale = false;
    if (PROJ) {
        if (n0 < 2048)      { Bp = B0 + n0;          ldB = 2048; Cp = C0 + n0;                ldC = 2048; doscale = true; }
        else if (n0 < 2560) { Bp = B1 + (n0 - 2048); ldB = 512;  Cp = C1 + (n0 - 2048);       ldC = 1024; }
        else                { Bp = B2 + (n0 - 2560); ldB = 512;  Cp = C1 + (n0 - 2560 + 512); ldC = 1024; }
    } else { Bp = B0 + n0; ldB = 2048; Cp = C0 + n0; ldC = 2048; }

    const int kiters = K / GBK;

    float acc[4][8][4];
#pragma unroll
    for (int i = 0; i < 4; i++)
#pragma unroll
        for (int j = 0; j < 8; j++)
#pragma unroll
            for (int r = 0; r < 4; r++) acc[i][j][r] = 0.f;

#define G_LOAD(s, kc) do {                                                        \
        uint32_t _ab = smb + (s) * (STG_F * 4);                                   \
        uint32_t _bb = _ab + AS_F * 4;                                            \
        _Pragma("unroll")                                                         \
        for (int _i = 0; _i < 4; _i++) {                                          \
            int _e = tid + _i * 256, _r = _e >> 3, _kq = _e & 7;                  \
            CP_ASYNC16(_ab + (_r * ALD + _kq * 4) * 4,                            \
                (const void*)(A + (size_t)(m0 + _r) * K + (kc) * GBK + _kq * 4)); \
        }                                                                         \
        _Pragma("unroll")                                                         \
        for (int _i = 0; _i < 8; _i++) {                                          \
            int _e = tid + _i * 256, _r = _e >> 6, _cq = _e & 63;                 \
            CP_ASYNC16(_bb + (_r * BLD + _cq * 4) * 4,                            \
                (const void*)(Bp + (size_t)((kc) * GBK + _r) * ldB + _cq * 4));   \
        }                                                                         \
    } while (0)

    G_LOAD(0, 0); CP_COMMIT();
    G_LOAD(1, 1); CP_COMMIT();

    for (int it = 0; it < kiters; it++) {
        CP_WAIT1();
        __syncthreads();
        if (it + 2 < kiters) G_LOAD((it + 2) % 3, it + 2);
        CP_COMMIT();

        const float* As = smg + (it % 3) * STG_F;
        const float* Bs = As + AS_F;

#pragma unroll
        for (int ks = 0; ks < 4; ks++) {
            const int k8 = ks * 8;
            uint32_t af[4][4], bf[8][2];
#pragma unroll
            for (int mf = 0; mf < 4; mf++) {
                const float* p = As + (wm + mf * 16 + lq) * ALD + k8 + lr;
                af[mf][0] = __float_as_uint(p[0]);
                af[mf][1] = __float_as_uint(p[8 * ALD]);
                af[mf][2] = __float_as_uint(p[4]);
                af[mf][3] = __float_as_uint(p[8 * ALD + 4]);
            }
#pragma unroll
            for (int nf = 0; nf < 8; nf++) {
                const float* p = Bs + (k8 + lr) * BLD + wn + nf * 8 + lq;
                bf[nf][0] = __float_as_uint(p[0]);
                bf[nf][1] = __float_as_uint(p[4 * BLD]);
            }
#pragma unroll
            for (int mf = 0; mf < 4; mf++)
#pragma unroll
                for (int nf = 0; nf < 8; nf++)
                    mma_tf32(acc[mf][nf], af[mf], bf[nf]);
        }
        __syncthreads();
    }

    // epilogue
#pragma unroll
    for (int mf = 0; mf < 4; mf++) {
        const int row = m0 + wm + mf * 16 + lq;
#pragma unroll
        for (int nf = 0; nf < 8; nf++) {
            const int col = wn + nf * 8 + 2 * lr;
            float v0 = acc[mf][nf][0], v1 = acc[mf][nf][1];
            float v2 = acc[mf][nf][2], v3 = acc[mf][nf][3];
            if (PROJ) {
                if (doscale) { v0 *= SCALE; v1 *= SCALE; v2 *= SCALE; v3 *= SCALE; }
                v0 = tf32r(v0); v1 = tf32r(v1); v2 = tf32r(v2); v3 = tf32r(v3);
            } else {
                float2 b = *(const float2*)(bias + n0 + col);
                v0 += b.x; v1 += b.y; v2 += b.x; v3 += b.y;
            }
            *(float2*)(Cp + (size_t)row * ldC + col)       = make_float2(v0, v1);
            *(float2*)(Cp + (size_t)(row + 8) * ldC + col) = make_float2(v2, v3);
        }
    }
#undef G_LOAD
}

// ---------------- tf32 mma flash-attention: split-softmax 4x2 warps ----------
// 256 threads (8 warps). CTA: (batch, head) x 128 q-rows.
// Warp (r, c): 32 q-rows (wq = r*32), 32-key half (koff = c*32) of each 64-key
// tile; private (m, l, O) merged at CTA end via retired Q smem.
#define QROW 132
#define KROW 132
#define VROW 136
#define QS_F (128 * QROW)                     /* 16896 */
#define KS_ST (64 * KROW)                     /* 8448 */
#define VS_ST (64 * VROW)                     /* 8704 */
#define ATTN_SMEM ((QS_F + 2 * KS_ST + 2 * VS_ST) * 4)   /* 204800 B */

__global__ __launch_bounds__(256, 1) void attn_mma(
    const float* __restrict__ Q, const float* __restrict__ KV,
    float* __restrict__ C)
{
    extern __shared__ float sm[];
    float* Qs = sm;
    const int tid = threadIdx.x;
    const int wid = tid >> 5, l = tid & 31;
    const int lq = l >> 2, lr = l & 3;
    const int wr = wid >> 1, wc = wid & 1;
    const int wq = wr * 32;
    const int koff = wc * 32;

    const int qc = gridDim.x - 1 - blockIdx.x;   // long CTAs first
    const int hh = blockIdx.y;
    const int bi = hh >> 4;
    const int gi = (hh >> 2) & 3;
    const int hi = hh & 3;
    const int qcol = (gi * HPG + hi) * HD;
    const int kcolK = gi * HD;
    const int kcolV = 512 + gi * HD;
    const size_t rowbase = (size_t)bi * SEQ;
    const int qbase = qc * 128;
    const uint32_t smb = smem_u32(sm);

    // ---- load Q tile [128 x 128] into smem ----
    for (int i = tid; i < 128 * 32; i += 256) {
        int r = i >> 5, c4 = (i & 31) << 2;
        *(float4*)&Qs[r * QROW + c4] =
            *(const float4*)(Q + (rowbase + qbase + r) * (size_t)D_OUT + qcol + c4);
    }

    float o[2][16][4];
#pragma unroll
    for (int mf = 0; mf < 2; mf++)
#pragma unroll
        for (int i = 0; i < 16; i++)
#pragma unroll
            for (int r = 0; r < 4; r++) o[mf][i][r] = 0.f;
    float mm[2][2], ll[2][2];
#pragma unroll
    for (int mf = 0; mf < 2; mf++) {
        mm[mf][0] = -CUDART_INF_F; mm[mf][1] = -CUDART_INF_F;
        ll[mf][0] = 0.f; ll[mf][1] = 0.f;
    }

    const int jmax = 2 * qc + 1;

#define KV_LOAD(ss, jj) do {                                                     \
        uint32_t _kb = smb + (QS_F + (ss) * KS_ST) * 4;                          \
        uint32_t _vb = smb + (QS_F + 2 * KS_ST + (ss) * VS_ST) * 4;              \
        const float* _gk = KV + (rowbase + (jj) * 64) * KVD + kcolK;             \
        const float* _gv = KV + (rowbase + (jj) * 64) * KVD + kcolV;             \
        _Pragma("unroll")                                                        \
        for (int _u = 0; _u < 8; _u++) {                                         \
            int _e = tid + _u * 256, _r = _e >> 5, _c4 = (_e & 31) << 2;         \
            CP_ASYNC16(_kb + (_r * KROW + _c4) * 4,                              \
                       (const void*)(_gk + (size_t)_r * KVD + _c4));             \
            CP_ASYNC16(_vb + (_r * VROW + _c4) * 4,                              \
                       (const void*)(_gv + (size_t)_r * KVD + _c4));             \
        }                                                                        \
    } while (0)

    KV_LOAD(0, 0); CP_COMMIT();

    for (int j = 0; j <= jmax; j++) {
        CP_WAIT0();
        __syncthreads();   // KV stage ready; also covers Q visibility on j=0
        if (j < jmax) KV_LOAD((j + 1) & 1, j + 1);
        CP_COMMIT();

        const int st = j & 1;
        const float* Ks = sm + QS_F + st * KS_ST;
        const float* Vs = sm + QS_F + 2 * KS_ST + st * VS_ST;
        const int kb = j * 64 + koff;             // this warp's first key
        if (kb > qbase + wq + 31) continue;       // warp's half fully masked

        // ---- S = Q @ K^T : 32 q-rows x 32 keys ----
        float s_[2][4][4];
#pragma unroll
        for (int mf = 0; mf < 2; mf++)
#pragma unroll
            for (int nf = 0; nf < 4; nf++)
#pragma unroll
                for (int r = 0; r < 4; r++) s_[mf][nf][r] = 0.f;

#pragma unroll
        for (int kf = 0; kf < 16; kf++) {
            uint32_t qa[2][4];
#pragma unroll
            for (int mf = 0; mf < 2; mf++) {
                const float* qp = Qs + (wq + mf * 16 + lq) * QROW + kf * 8 + lr;
                qa[mf][0] = __float_as_uint(qp[0]);
                qa[mf][1] = __float_as_uint(qp[8 * QROW]);
                qa[mf][2] = __float_as_uint(qp[4]);
                qa[mf][3] = __float_as_uint(qp[8 * QROW + 4]);
            }
#pragma unroll
            for (int nf = 0; nf < 4; nf++) {
                const float* kp = Ks + (koff + nf * 8 + lq) * KROW + kf * 8 + lr;
                uint32_t b[2] = { __float_as_uint(kp[0]), __float_as_uint(kp[4]) };
                mma_tf32(s_[0][nf], qa[0], b);
                mma_tf32(s_[1][nf], qa[1], b);
            }
        }

        // ---- per-warp softmax over its 32-key half ----
        const bool needmask = (kb + 31 > qbase + wq);
#pragma unroll
        for (int mf = 0; mf < 2; mf++) {
            const int gr0 = qbase + wq + mf * 16 + lq;
            const int gr1 = gr0 + 8;
            float mx0 = -CUDART_INF_F, mx1 = -CUDART_INF_F;
#pragma unroll
            for (int nf = 0; nf < 4; nf++) {
                if (needmask) {
                    const int c0 = kb + nf * 8 + 2 * lr;
                    if (c0 > gr0)     s_[mf][nf][0] = -CUDART_INF_F;
                    if (c0 + 1 > gr0) s_[mf][nf][1] = -CUDART_INF_F;
                    if (c0 > gr1)     s_[mf][nf][2] = -CUDART_INF_F;
                    if (c0 + 1 > gr1) s_[mf][nf][3] = -CUDART_INF_F;
                }
                mx0 = fmaxf(mx0, fmaxf(s_[mf][nf][0], s_[mf][nf][1]));
                mx1 = fmaxf(mx1, fmaxf(s_[mf][nf][2], s_[mf][nf][3]));
            }
#pragma unroll
            for (int msk = 1; msk < 4; msk <<= 1) {
                mx0 = fmaxf(mx0, __shfl_xor_sync(0xffffffffu, mx0, msk));
                mx1 = fmaxf(mx1, __shfl_xor_sync(0xffffffffu, mx1, msk));
            }
            const float nm0 = fmaxf(mm[mf][0], mx0);
            const float nm1 = fmaxf(mm[mf][1], mx1);
            const float al0 = __expf(mm[mf][0] - nm0);
            const float al1 = __expf(mm[mf][1] - nm1);
            mm[mf][0] = nm0; mm[mf][1] = nm1;

            float sm0 = 0.f, sm1 = 0.f;
#pragma unroll
            for (int nf = 0; nf < 4; nf++) {
                float p0 = tf32r(__expf(s_[mf][nf][0] - nm0));
                float p1 = tf32r(__expf(s_[mf][nf][1] - nm0));
                float p2 = tf32r(__expf(s_[mf][nf][2] - nm1));
                float p3 = tf32r(__expf(s_[mf][nf][3] - nm1));
                s_[mf][nf][0] = p0; s_[mf][nf][1] = p1;
                s_[mf][nf][2] = p2; s_[mf][nf][3] = p3;
                sm0 += p0 + p1; sm1 += p2 + p3;
            }
#pragma unroll
            for (int msk = 1; msk < 4; msk <<= 1) {
                sm0 += __shfl_xor_sync(0xffffffffu, sm0, msk);
                sm1 += __shfl_xor_sync(0xffffffffu, sm1, msk);
            }
            ll[mf][0] = ll[mf][0] * al0 + sm0;
            ll[mf][1] = ll[mf][1] * al1 + sm1;
#pragma unroll
            for (int nf = 0; nf < 16; nf++) {
                o[mf][nf][0] *= al0; o[mf][nf][1] *= al0;
                o[mf][nf][2] *= al1; o[mf][nf][3] *= al1;
            }
        }

        // ---- O += P @ V : P a-frags via shuffle transpose of s_ ----
        const int src0 = (lq << 2) + (lr >> 1);
        const int src1 = src0 + 2;
        const bool odd = (lr & 1);
#pragma unroll
        for (int kf = 0; kf < 4; kf++) {
            uint32_t aP[2][4];
#pragma unroll
            for (int mf = 0; mf < 2; mf++) {
                float t00 = __shfl_sync(0xffffffffu, s_[mf][kf][0], src0);
                float t01 = __shfl_sync(0xffffffffu, s_[mf][kf][1], src0);
                float t20 = __shfl_sync(0xffffffffu, s_[mf][kf][2], src0);
                float t21 = __shfl_sync(0xffffffffu, s_[mf][kf][3], src0);
                float t40 = __shfl_sync(0xffffffffu, s_[mf][kf][0], src1);
                float t41 = __shfl_sync(0xffffffffu, s_[mf][kf][1], src1);
                float t60 = __shfl_sync(0xffffffffu, s_[mf][kf][2], src1);
                float t61 = __shfl_sync(0xffffffffu, s_[mf][kf][3], src1);
                aP[mf][0] = __float_as_uint(odd ? t01 : t00);
                aP[mf][1] = __float_as_uint(odd ? t21 : t20);
                aP[mf][2] = __float_as_uint(odd ? t41 : t40);
                aP[mf][3] = __float_as_uint(odd ? t61 : t60);
            }
#pragma unroll
            for (int nf = 0; nf < 16; nf++) {
                const float* vp = Vs + (koff + kf * 8 + lr) * VROW + nf * 8 + lq;
                uint32_t b[2] = { __float_as_uint(vp[0]),
                                  __float_as_uint(vp[4 * VROW]) };
                mma_tf32(o[0][nf], aP[0], b);
                mma_tf32(o[1][nf], aP[1], b);
            }
        }
    }

    // ---- merge the two key-halves (wc=1 publishes, wc=0 combines) ----
    float* Ox = sm;                          // reuse Q area: [4][32][132]
    float* St = sm + QS_F;                   // stats [4][32][2] (in K area)
    __syncthreads();
    if (wc == 1) {
        float* ob = Ox + wr * 32 * 132;
#pragma unroll
        for (int mf = 0; mf < 2; mf++) {
            const int row0 = mf * 16 + lq;
#pragma unroll
            for (int nf = 0; nf < 16; nf++) {
                const int col = nf * 8 + 2 * lr;
                *(float2*)&ob[row0 * 132 + col]       = make_float2(o[mf][nf][0], o[mf][nf][1]);
                *(float2*)&ob[(row0 + 8) * 132 + col] = make_float2(o[mf][nf][2], o[mf][nf][3]);
            }
            if (lr == 0) {
                float* st = St + (wr * 32 + row0) * 2;
                st[0] = mm[mf][0]; st[1] = ll[mf][0];
                st[16] = mm[mf][1]; st[17] = ll[mf][1];   // row0+8
            }
        }
    }
    __syncthreads();
    if (wc == 0) {
        const float* ob = Ox + wr * 32 * 132;
#pragma unroll
        for (int mf = 0; mf < 2; mf++) {
            const int row0 = mf * 16 + lq;
            const float* st = St + (wr * 32 + row0) * 2;
            const float mo0 = st[0],  lo0 = st[1];
            const float mo1 = st[16], lo1 = st[17];
            const float M0 = fmaxf(mm[mf][0], mo0);
            const float M1 = fmaxf(mm[mf][1], mo1);
            const float as0 = __expf(mm[mf][0] - M0), ao0 = __expf(mo0 - M0);
            const float as1 = __expf(mm[mf][1] - M1), ao1 = __expf(mo1 - M1);
            const float inv0 = 1.f / (ll[mf][0] * as0 + lo0 * ao0);
            const float inv1 = 1.f / (ll[mf][1] * as1 + lo1 * ao1);
            const float fs0 = as0 * inv0, fo0 = ao0 * inv0;
            const float fs1 = as1 * inv1, fo1 = ao1 * inv1;
            const size_t r0 = rowbase + qbase + wq + row0;
            const size_t r1 = r0 + 8;
#pragma unroll
            for (int nf = 0; nf < 16; nf++) {
                const int col = nf * 8 + 2 * lr;
                float2 q0 = *(const float2*)&ob[row0 * 132 + col];
                float2 q1 = *(const float2*)&ob[(row0 + 8) * 132 + col];
                *(float2*)(C + r0 * D_OUT + qcol + col) =
                    make_float2(tf32r(o[mf][nf][0] * fs0 + q0.x * fo0),
                                tf32r(o[mf][nf][1] * fs0 + q0.y * fo0));
                *(float2*)(C + r1 * D_OUT + qcol + col) =
                    make_float2(tf32r(o[mf][nf][2] * fs1 + q1.x * fo1),
                                tf32r(o[mf][nf][3] * fs1 + q1.y * fo1));
            }
        }
    }
#undef KV_LOAD
}

// ---------------------------------------------------------------------------
extern "C" void kernel_launch(void* const* d_in, const int* in_sizes, int n_in,
                              void* d_out, int out_size)
{
    const float* x  = (const float*)d_in[0];
    const float* Wq = (const float*)d_in[1];
    const float* Wk = (const float*)d_in[2];
    const float* Wv = (const float*)d_in[3];
    const float* Wo = (const float*)d_in[4];
    const float* bo = (const float*)d_in[5];

    const int M = in_sizes[0] / D_IN;   // 4096
    const int B = M / SEQ;              // 2

    float *Xr, *Wqr, *Wkr, *Wvr, *Wor, *Qp, *KVp, *Cp;
    cudaGetSymbolAddress((void**)&Xr,  g_X);
    cudaGetSymbolAddress((void**)&Wqr, g_Wq);
    cudaGetSymbolAddress((void**)&Wkr, g_Wk);
    cudaGetSymbolAddress((void**)&Wvr, g_Wv);
    cudaGetSymbolAddress((void**)&Wor, g_Wo);
    cudaGetSymbolAddress((void**)&Qp,  g_Q);
    cudaGetSymbolAddress((void**)&KVp, g_KV);
    cudaGetSymbolAddress((void**)&Cp,  g_C);

    cudaFuncSetAttribute(gemm_k<true>,
                         cudaFuncAttributeMaxDynamicSharedMemorySize, GEMM_SMEM);
    cudaFuncSetAttribute(gemm_k<false>,
                         cudaFuncAttributeMaxDynamicSharedMemorySize, GEMM_SMEM);
    cudaFuncSetAttribute(attn_mma,
                         cudaFuncAttributeMaxDynamicSharedMemorySize, ATTN_SMEM);

    // fused prepass: tf32-round x and all weights (one launch)
    round_all<<<592, 256>>>(x, Xr, Wq, Wqr, Wk, Wkr, Wv, Wvr, Wo, Wor, M);

    // fused QKV projection: N = 2048 (Q) + 512 (K) + 512 (V) = 3072
    gemm_k<true><<<dim3(12, M / 128), 256, GEMM_SMEM>>>(
        Xr, Wqr, Wkr, Wvr, Qp, KVp, nullptr, M, D_IN);

    attn_mma<<<dim3(SEQ / 128, B * 16), 256, ATTN_SMEM>>>(Qp, KVp, Cp);

    // output projection + bias
    gemm_k<false><<<dim3(8, M / 128), 256, GEMM_SMEM>>>(
        Cp, Wor, nullptr, nullptr, (float*)d_out, nullptr, bo, M, D_OUT);
}

// round 7
// speedup vs baseline: 1.2390x; 1.0444x over previous
#include <cuda_runtime.h>
#include <cuda_bf16.h>
#include <math_constants.h>
#include <cstdint>

#define D_IN   2048
#define D_OUT  2048
#define HD     128
#define NG     4
#define HPG    4
#define SEQ    2048
#define KVD    1024   /* fused K|V buffer width */

// ---------------- scratch (no cudaMalloc allowed) ----------------
__device__ float g_X [4096 * 2048];   // x, tf32-rounded
__device__ float g_Wq[2048 * 2048];
__device__ float g_Wk[2048 * 512];
__device__ float g_Wv[2048 * 512];
__device__ float g_Wo[2048 * 2048];
__device__ float g_Q [4096 * 2048];   // q proj, scaled + tf32
__device__ float g_KV[4096 * 1024];   // [K | V], tf32
__device__ float g_C [4096 * 2048];   // ctx, tf32

// ---------------- helpers ----------------
__device__ __forceinline__ uint32_t f2tf(float x) {
    uint32_t u;
    asm("cvt.rna.tf32.f32 %0, %1;" : "=r"(u) : "f"(x));
    return u;
}
__device__ __forceinline__ float tf32r(float x) { return __uint_as_float(f2tf(x)); }

__device__ __forceinline__ void mma_tf32(float* d, const uint32_t* a, const uint32_t* b) {
    asm volatile(
        "mma.sync.aligned.m16n8k8.row.col.f32.tf32.tf32.f32 "
        "{%0,%1,%2,%3}, {%4,%5,%6,%7}, {%8,%9}, {%0,%1,%2,%3};"
        : "+f"(d[0]), "+f"(d[1]), "+f"(d[2]), "+f"(d[3])
        : "r"(a[0]), "r"(a[1]), "r"(a[2]), "r"(a[3]), "r"(b[0]), "r"(b[1]));
}
__device__ __forceinline__ uint32_t smem_u32(const void* p) {
    uint32_t a;
    asm("{ .reg .u64 t; cvta.to.shared.u64 t, %1; cvt.u32.u64 %0, t; }" : "=r"(a) : "l"(p));
    return a;
}
#define CP_ASYNC16(dst, src) \
    asm volatile("cp.async.cg.shared.global [%0], [%1], 16;" :: "r"(dst), "l"(src) : "memory")
#define CP_COMMIT() asm volatile("cp.async.commit_group;" ::: "memory")
#define CP_WAIT0()  asm volatile("cp.async.wait_group 0;" ::: "memory")

#define SCALE 0.08838834764831845f   /* 1/sqrt(128) */

// ---------------- prepass: fused tf32 rounding of x + all weights ----------------
__global__ void round_all(const float* __restrict__ x,  float* __restrict__ xr,
                          const float* __restrict__ wq, float* __restrict__ wqr,
                          const float* __restrict__ wk, float* __restrict__ wkr,
                          const float* __restrict__ wv, float* __restrict__ wvr,
                          const float* __restrict__ wo, float* __restrict__ wor,
                          int Mtot)
{
    const size_t n_x = (size_t)Mtot * D_IN / 4;
    const size_t n_q = (size_t)D_IN * D_OUT / 4;
    const size_t n_k = (size_t)D_IN * 512 / 4;
    const size_t stride = (size_t)gridDim.x * blockDim.x;
    const size_t i0 = (size_t)blockIdx.x * blockDim.x + threadIdx.x;

    const float4* src[5] = { (const float4*)x, (const float4*)wq, (const float4*)wk,
                             (const float4*)wv, (const float4*)wo };
    float4* dst[5] = { (float4*)xr, (float4*)wqr, (float4*)wkr, (float4*)wvr, (float4*)wor };
    const size_t cnt[5] = { n_x, n_q, n_k, n_k, n_q };

#pragma unroll
    for (int s = 0; s < 5; s++) {
        for (size_t i = i0; i < cnt[s]; i += stride) {
            float4 v = src[s][i];
            v.x = tf32r(v.x); v.y = tf32r(v.y); v.z = tf32r(v.z); v.w = tf32r(v.w);
            dst[s][i] = v;
        }
    }
}

// ------- tf32 mma GEMM: CTA 128x256, 8 warps @ 64x64, BK=64, 2-stage ---------
#define GBK 64
#define ALD 68                          /* A smem row stride (floats) */
#define BLD 264                         /* B smem row stride (floats) */
#define AS_F (128 * ALD)                /* 8704 */
#define BS_F (GBK * BLD)                /* 16896 */
#define STG_F (AS_F + BS_F)             /* 25600 */
#define GEMM_SMEM (2 * STG_F * 4)       /* 204800 B */

template <bool PROJ>
__global__ __launch_bounds__(256, 1) void gemm_k(
    const float* __restrict__ A,
    const float* __restrict__ B0, const float* __restrict__ B1, const float* __restrict__ B2,
    float* __restrict__ C0, float* __restrict__ C1,
    const float* __restrict__ bias, int M, int K)
{
    extern __shared__ float smg[];
    const int tid = threadIdx.x;
    const int wid = tid >> 5, l = tid & 31;
    const int lq = l >> 2, lr = l & 3;
    const int m0 = blockIdx.y * 128;
    const int n0 = blockIdx.x * 256;
    const int wm = (wid & 1) * 64, wn = (wid >> 1) * 64;
    const uint32_t smb = smem_u32(smg);

    const float* Bp; int ldB; float* Cp; int ldC; bool doscale = false;
    if (PROJ) {
        if (n0 < 2048)      { Bp = B0 + n0;          ldB = 2048; Cp = C0 + n0;                ldC = 2048; doscale = true; }
        else if (n0 < 2560) { Bp = B1 + (n0 - 2048); ldB = 512;  Cp = C1 + (n0 - 2048);       ldC = 1024; }
        else                { Bp = B2 + (n0 - 2560); ldB = 512;  Cp = C1 + (n0 - 2560 + 512); ldC = 1024; }
    } else { Bp = B0 + n0; ldB = 2048; Cp = C0 + n0; ldC = 2048; }

    const int kiters = K / GBK;   // 32

    float acc[4][8][4];
#pragma unroll
    for (int i = 0; i < 4; i++)
#pragma unroll
        for (int j = 0; j < 8; j++)
#pragma unroll
            for (int r = 0; r < 4; r++) acc[i][j][r] = 0.f;

    // A tile 128x64: 2048 float4 -> 8/thread.  B tile 64x256: 4096 float4 -> 16/thread.
#define G_LOAD(s, kc) do {                                                        \
        uint32_t _ab = smb + (s) * (STG_F * 4);                                   \
        uint32_t _bb = _ab + AS_F * 4;                                            \
        _Pragma("unroll")                                                         \
        for (int _i = 0; _i < 8; _i++) {                                          \
            int _e = tid + _i * 256, _r = _e >> 4, _kq = _e & 15;                 \
            CP_ASYNC16(_ab + (_r * ALD + _kq * 4) * 4,                            \
                (const void*)(A + (size_t)(m0 + _r) * K + (kc) * GBK + _kq * 4)); \
        }                                                                         \
        _Pragma("unroll")                                                         \
        for (int _i = 0; _i < 16; _i++) {                                         \
            int _e = tid + _i * 256, _r = _e >> 6, _cq = _e & 63;                 \
            CP_ASYNC16(_bb + (_r * BLD + _cq * 4) * 4,                            \
                (const void*)(Bp + (size_t)((kc) * GBK + _r) * ldB + _cq * 4));   \
        }                                                                         \
    } while (0)

    G_LOAD(0, 0); CP_COMMIT();

    for (int it = 0; it < kiters; it++) {
        CP_WAIT0();
        __syncthreads();
        if (it + 1 < kiters) { G_LOAD((it + 1) & 1, it + 1); CP_COMMIT(); }

        const float* As = smg + (it & 1) * STG_F;
        const float* Bs = As + AS_F;

#pragma unroll
        for (int ks = 0; ks < 8; ks++) {
            const int k8 = ks * 8;
            uint32_t af[4][4], bf[8][2];
#pragma unroll
            for (int mf = 0; mf < 4; mf++) {
                const float* p = As + (wm + mf * 16 + lq) * ALD + k8 + lr;
                af[mf][0] = __float_as_uint(p[0]);
                af[mf][1] = __float_as_uint(p[8 * ALD]);
                af[mf][2] = __float_as_uint(p[4]);
                af[mf][3] = __float_as_uint(p[8 * ALD + 4]);
            }
#pragma unroll
            for (int nf = 0; nf < 8; nf++) {
                const float* p = Bs + (k8 + lr) * BLD + wn + nf * 8 + lq;
                bf[nf][0] = __float_as_uint(p[0]);
                bf[nf][1] = __float_as_uint(p[4 * BLD]);
            }
#pragma unroll
            for (int mf = 0; mf < 4; mf++)
#pragma unroll
                for (int nf = 0; nf < 8; nf++)
                    mma_tf32(acc[mf][nf], af[mf], bf[nf]);
        }
    }

    // epilogue
#pragma unroll
    for (int mf = 0; mf < 4; mf++) {
        const int row = m0 + wm + mf * 16 + lq;
#pragma unroll
        for (int nf = 0; nf < 8; nf++) {
            const int col = wn + nf * 8 + 2 * lr;
            float v0 = acc[mf][nf][0], v1 = acc[mf][nf][1];
            float v2 = acc[mf][nf][2], v3 = acc[mf][nf][3];
            if (PROJ) {
                if (doscale) { v0 *= SCALE; v1 *= SCALE; v2 *= SCALE; v3 *= SCALE; }
                v0 = tf32r(v0); v1 = tf32r(v1); v2 = tf32r(v2); v3 = tf32r(v3);
            } else {
                float2 b = *(const float2*)(bias + n0 + col);
                v0 += b.x; v1 += b.y; v2 += b.x; v3 += b.y;
            }
            *(float2*)(Cp + (size_t)row * ldC + col)       = make_float2(v0, v1);
            *(float2*)(Cp + (size_t)(row + 8) * ldC + col) = make_float2(v2, v3);
        }
    }
#undef G_LOAD
}

// ---------------- tf32 mma flash-attention: split-softmax 4x2 warps ----------
#define QROW 132
#define KROW 132
#define VROW 136
#define QS_F (128 * QROW)                     /* 16896 */
#define KS_ST (64 * KROW)                     /* 8448 */
#define VS_ST (64 * VROW)                     /* 8704 */
#define ATTN_SMEM ((QS_F + 2 * KS_ST + 2 * VS_ST) * 4)   /* 204800 B */

__global__ __launch_bounds__(256, 1) void attn_mma(
    const float* __restrict__ Q, const float* __restrict__ KV,
    float* __restrict__ C)
{
    extern __shared__ float sm[];
    float* Qs = sm;
    const int tid = threadIdx.x;
    const int wid = tid >> 5, l = tid & 31;
    const int lq = l >> 2, lr = l & 3;
    const int wr = wid >> 1, wc = wid & 1;
    const int wq = wr * 32;
    const int koff = wc * 32;

    const int qc = gridDim.x - 1 - blockIdx.x;   // long CTAs first
    const int hh = blockIdx.y;
    const int bi = hh >> 4;
    const int gi = (hh >> 2) & 3;
    const int hi = hh & 3;
    const int qcol = (gi * HPG + hi) * HD;
    const int kcolK = gi * HD;
    const int kcolV = 512 + gi * HD;
    const size_t rowbase = (size_t)bi * SEQ;
    const int qbase = qc * 128;
    const uint32_t smb = smem_u32(sm);

    // ---- load Q tile [128 x 128] into smem ----
    for (int i = tid; i < 128 * 32; i += 256) {
        int r = i >> 5, c4 = (i & 31) << 2;
        *(float4*)&Qs[r * QROW + c4] =
            *(const float4*)(Q + (rowbase + qbase + r) * (size_t)D_OUT + qcol + c4);
    }

    float o[2][16][4];
#pragma unroll
    for (int mf = 0; mf < 2; mf++)
#pragma unroll
        for (int i = 0; i < 16; i++)
#pragma unroll
            for (int r = 0; r < 4; r++) o[mf][i][r] = 0.f;
    float mm[2][2], ll[2][2];
#pragma unroll
    for (int mf = 0; mf < 2; mf++) {
        mm[mf][0] = -CUDART_INF_F; mm[mf][1] = -CUDART_INF_F;
        ll[mf][0] = 0.f; ll[mf][1] = 0.f;
    }

    const int jmax = 2 * qc + 1;

#define KV_LOAD(ss, jj) do {                                                     \
        uint32_t _kb = smb + (QS_F + (ss) * KS_ST) * 4;                          \
        uint32_t _vb = smb + (QS_F + 2 * KS_ST + (ss) * VS_ST) * 4;              \
        const float* _gk = KV + (rowbase + (jj) * 64) * KVD + kcolK;             \
        const float* _gv = KV + (rowbase + (jj) * 64) * KVD + kcolV;             \
        _Pragma("unroll")                                                        \
        for (int _u = 0; _u < 8; _u++) {                                         \
            int _e = tid + _u * 256, _r = _e >> 5, _c4 = (_e & 31) << 2;         \
            CP_ASYNC16(_kb + (_r * KROW + _c4) * 4,                              \
                       (const void*)(_gk + (size_t)_r * KVD + _c4));             \
            CP_ASYNC16(_vb + (_r * VROW + _c4) * 4,                              \
                       (const void*)(_gv + (size_t)_r * KVD + _c4));             \
        }                                                                        \
    } while (0)

    KV_LOAD(0, 0); CP_COMMIT();

    for (int j = 0; j <= jmax; j++) {
        CP_WAIT0();
        __syncthreads();   // KV stage ready; also covers Q visibility on j=0
        if (j < jmax) KV_LOAD((j + 1) & 1, j + 1);
        CP_COMMIT();

        const int st = j & 1;
        const float* Ks = sm + QS_F + st * KS_ST;
        const float* Vs = sm + QS_F + 2 * KS_ST + st * VS_ST;
        const int kb = j * 64 + koff;             // this warp's first key
        if (kb > qbase + wq + 31) continue;       // warp's half fully masked

        // ---- S = Q @ K^T : 32 q-rows x 32 keys ----
        float s_[2][4][4];
#pragma unroll
        for (int mf = 0; mf < 2; mf++)
#pragma unroll
            for (int nf = 0; nf < 4; nf++)
#pragma unroll
                for (int r = 0; r < 4; r++) s_[mf][nf][r] = 0.f;

#pragma unroll
        for (int kf = 0; kf < 16; kf++) {
            uint32_t qa[2][4];
#pragma unroll
            for (int mf = 0; mf < 2; mf++) {
                const float* qp = Qs + (wq + mf * 16 + lq) * QROW + kf * 8 + lr;
                qa[mf][0] = __float_as_uint(qp[0]);
                qa[mf][1] = __float_as_uint(qp[8 * QROW]);
                qa[mf][2] = __float_as_uint(qp[4]);
                qa[mf][3] = __float_as_uint(qp[8 * QROW + 4]);
            }
#pragma unroll
            for (int nf = 0; nf < 4; nf++) {
                const float* kp = Ks + (koff + nf * 8 + lq) * KROW + kf * 8 + lr;
                uint32_t b[2] = { __float_as_uint(kp[0]), __float_as_uint(kp[4]) };
                mma_tf32(s_[0][nf], qa[0], b);
                mma_tf32(s_[1][nf], qa[1], b);
            }
        }

        // ---- per-warp softmax over its 32-key half ----
        const bool needmask = (kb + 31 > qbase + wq);
#pragma unroll
        for (int mf = 0; mf < 2; mf++) {
            const int gr0 = qbase + wq + mf * 16 + lq;
            const int gr1 = gr0 + 8;
            float mx0 = -CUDART_INF_F, mx1 = -CUDART_INF_F;
#pragma unroll
            for (int nf = 0; nf < 4; nf++) {
                if (needmask) {
                    const int c0 = kb + nf * 8 + 2 * lr;
                    if (c0 > gr0)     s_[mf][nf][0] = -CUDART_INF_F;
                    if (c0 + 1 > gr0) s_[mf][nf][1] = -CUDART_INF_F;
                    if (c0 > gr1)     s_[mf][nf][2] = -CUDART_INF_F;
                    if (c0 + 1 > gr1) s_[mf][nf][3] = -CUDART_INF_F;
                }
                mx0 = fmaxf(mx0, fmaxf(s_[mf][nf][0], s_[mf][nf][1]));
                mx1 = fmaxf(mx1, fmaxf(s_[mf][nf][2], s_[mf][nf][3]));
            }
#pragma unroll
            for (int msk = 1; msk < 4; msk <<= 1) {
                mx0 = fmaxf(mx0, __shfl_xor_sync(0xffffffffu, mx0, msk));
                mx1 = fmaxf(mx1, __shfl_xor_sync(0xffffffffu, mx1, msk));
            }
            const float nm0 = fmaxf(mm[mf][0], mx0);
            const float nm1 = fmaxf(mm[mf][1], mx1);
            const float al0 = __expf(mm[mf][0] - nm0);
            const float al1 = __expf(mm[mf][1] - nm1);
            mm[mf][0] = nm0; mm[mf][1] = nm1;

            float sm0 = 0.f, sm1 = 0.f;
#pragma unroll
            for (int nf = 0; nf < 4; nf++) {
                float p0 = tf32r(__expf(s_[mf][nf][0] - nm0));
                float p1 = tf32r(__expf(s_[mf][nf][1] - nm0));
                float p2 = tf32r(__expf(s_[mf][nf][2] - nm1));
                float p3 = tf32r(__expf(s_[mf][nf][3] - nm1));
                s_[mf][nf][0] = p0; s_[mf][nf][1] = p1;
                s_[mf][nf][2] = p2; s_[mf][nf][3] = p3;
                sm0 += p0 + p1; sm1 += p2 + p3;
            }
#pragma unroll
            for (int msk = 1; msk < 4; msk <<= 1) {
                sm0 += __shfl_xor_sync(0xffffffffu, sm0, msk);
                sm1 += __shfl_xor_sync(0xffffffffu, sm1, msk);
            }
            ll[mf][0] = ll[mf][0] * al0 + sm0;
            ll[mf][1] = ll[mf][1] * al1 + sm1;
#pragma unroll
            for (int nf = 0; nf < 16; nf++) {
                o[mf][nf][0] *= al0; o[mf][nf][1] *= al0;
                o[mf][nf][2] *= al1; o[mf][nf][3] *= al1;
            }
        }

        // ---- O += P @ V : P a-frags via shuffle transpose of s_ ----
        const int src0 = (lq << 2) + (lr >> 1);
        const int src1 = src0 + 2;
        const bool odd = (lr & 1);
#pragma unroll
        for (int kf = 0; kf < 4; kf++) {
            uint32_t aP[2][4];
#pragma unroll
            for (int mf = 0; mf < 2; mf++) {
                float t00 = __shfl_sync(0xffffffffu, s_[mf][kf][0], src0);
                float t01 = __shfl_sync(0xffffffffu, s_[mf][kf][1], src0);
                float t20 = __shfl_sync(0xffffffffu, s_[mf][kf][2], src0);
                float t21 = __shfl_sync(0xffffffffu, s_[mf][kf][3], src0);
                float t40 = __shfl_sync(0xffffffffu, s_[mf][kf][0], src1);
                float t41 = __shfl_sync(0xffffffffu, s_[mf][kf][1], src1);
                float t60 = __shfl_sync(0xffffffffu, s_[mf][kf][2], src1);
                float t61 = __shfl_sync(0xffffffffu, s_[mf][kf][3], src1);
                aP[mf][0] = __float_as_uint(odd ? t01 : t00);
                aP[mf][1] = __float_as_uint(odd ? t21 : t20);
                aP[mf][2] = __float_as_uint(odd ? t41 : t40);
                aP[mf][3] = __float_as_uint(odd ? t61 : t60);
            }
#pragma unroll
            for (int nf = 0; nf < 16; nf++) {
                const float* vp = Vs + (koff + kf * 8 + lr) * VROW + nf * 8 + lq;
                uint32_t b[2] = { __float_as_uint(vp[0]),
                                  __float_as_uint(vp[4 * VROW]) };
                mma_tf32(o[0][nf], aP[0], b);
                mma_tf32(o[1][nf], aP[1], b);
            }
        }
    }

    // ---- merge the two key-halves (wc=1 publishes, wc=0 combines) ----
    float* Ox = sm;                          // reuse Q area: [4][32][132]
    float* St = sm + QS_F;                   // stats [4][32][2] (in K area)
    __syncthreads();
    if (wc == 1) {
        float* ob = Ox + wr * 32 * 132;
#pragma unroll
        for (int mf = 0; mf < 2; mf++) {
            const int row0 = mf * 16 + lq;
#pragma unroll
            for (int nf = 0; nf < 16; nf++) {
                const int col = nf * 8 + 2 * lr;
                *(float2*)&ob[row0 * 132 + col]       = make_float2(o[mf][nf][0], o[mf][nf][1]);
                *(float2*)&ob[(row0 + 8) * 132 + col] = make_float2(o[mf][nf][2], o[mf][nf][3]);
            }
            if (lr == 0) {
                float* st = St + (wr * 32 + row0) * 2;
                st[0] = mm[mf][0]; st[1] = ll[mf][0];
                st[16] = mm[mf][1]; st[17] = ll[mf][1];   // row0+8
            }
        }
    }
    __syncthreads();
    if (wc == 0) {
        const float* ob = Ox + wr * 32 * 132;
#pragma unroll
        for (int mf = 0; mf < 2; mf++) {
            const int row0 = mf * 16 + lq;
            const float* st = St + (wr * 32 + row0) * 2;
            const float mo0 = st[0],  lo0 = st[1];
            const float mo1 = st[16], lo1 = st[17];
            const float M0 = fmaxf(mm[mf][0], mo0);
            const float M1 = fmaxf(mm[mf][1], mo1);
            const float as0 = __expf(mm[mf][0] - M0), ao0 = __expf(mo0 - M0);
            const float as1 = __expf(mm[mf][1] - M1), ao1 = __expf(mo1 - M1);
            const float inv0 = 1.f / (ll[mf][0] * as0 + lo0 * ao0);
            const float inv1 = 1.f / (ll[mf][1] * as1 + lo1 * ao1);
            const float fs0 = as0 * inv0, fo0 = ao0 * inv0;
            const float fs1 = as1 * inv1, fo1 = ao1 * inv1;
            const size_t r0 = rowbase + qbase + wq + row0;
            const size_t r1 = r0 + 8;
#pragma unroll
            for (int nf = 0; nf < 16; nf++) {
                const int col = nf * 8 + 2 * lr;
                float2 q0 = *(const float2*)&ob[row0 * 132 + col];
                float2 q1 = *(const float2*)&ob[(row0 + 8) * 132 + col];
                *(float2*)(C + r0 * D_OUT + qcol + col) =
                    make_float2(tf32r(o[mf][nf][0] * fs0 + q0.x * fo0),
                                tf32r(o[mf][nf][1] * fs0 + q0.y * fo0));
                *(float2*)(C + r1 * D_OUT + qcol + col) =
                    make_float2(tf32r(o[mf][nf][2] * fs1 + q1.x * fo1),
                                tf32r(o[mf][nf][3] * fs1 + q1.y * fo1));
            }
        }
    }
#undef KV_LOAD
}

// ---------------------------------------------------------------------------
extern "C" void kernel_launch(void* const* d_in, const int* in_sizes, int n_in,
                              void* d_out, int out_size)
{
    const float* x  = (const float*)d_in[0];
    const float* Wq = (const float*)d_in[1];
    const float* Wk = (const float*)d_in[2];
    const float* Wv = (const float*)d_in[3];
    const float* Wo = (const float*)d_in[4];
    const float* bo = (const float*)d_in[5];

    const int M = in_sizes[0] / D_IN;   // 4096
    const int B = M / SEQ;              // 2

    float *Xr, *Wqr, *Wkr, *Wvr, *Wor, *Qp, *KVp, *Cp;
    cudaGetSymbolAddress((void**)&Xr,  g_X);
    cudaGetSymbolAddress((void**)&Wqr, g_Wq);
    cudaGetSymbolAddress((void**)&Wkr, g_Wk);
    cudaGetSymbolAddress((void**)&Wvr, g_Wv);
    cudaGetSymbolAddress((void**)&Wor, g_Wo);
    cudaGetSymbolAddress((void**)&Qp,  g_Q);
    cudaGetSymbolAddress((void**)&KVp, g_KV);
    cudaGetSymbolAddress((void**)&Cp,  g_C);

    cudaFuncSetAttribute(gemm_k<true>,
                         cudaFuncAttributeMaxDynamicSharedMemorySize, GEMM_SMEM);
    cudaFuncSetAttribute(gemm_k<false>,
                         cudaFuncAttributeMaxDynamicSharedMemorySize, GEMM_SMEM);
    cudaFuncSetAttribute(attn_mma,
                         cudaFuncAttributeMaxDynamicSharedMemorySize, ATTN_SMEM);

    // fused prepass: tf32-round x and all weights (one launch)
    round_all<<<592, 256>>>(x, Xr, Wq, Wqr, Wk, Wkr, Wv, Wvr, Wo, Wor, M);

    // fused QKV projection: N = 2048 (Q) + 512 (K) + 512 (V) = 3072
    gemm_k<true><<<dim3(12, M / 128), 256, GEMM_SMEM>>>(
        Xr, Wqr, Wkr, Wvr, Qp, KVp, nullptr, M, D_IN);

    attn_mma<<<dim3(SEQ / 128, B * 16), 256, ATTN_SMEM>>>(Qp, KVp, Cp);

    // output projection + bias
    gemm_k<false><<<dim3(8, M / 128), 256, GEMM_SMEM>>>(
        Cp, Wor, nullptr, nullptr, (float*)d_out, nullptr, bo, M, D_OUT);
}

// round 8
// speedup vs baseline: 2.2041x; 1.7789x over previous
#include <cuda_runtime.h>
#include <cuda_fp16.h>
#include <math_constants.h>
#include <cstdint>

#define D_IN   2048
#define D_OUT  2048
#define HD     128
#define NG     4
#define HPG    4
#define SEQ    2048
#define GK     2048      /* K dim of every GEMM */

// ---------------- scratch (no cudaMalloc allowed) ----------------
__device__ __half g_Xh [4096 * 2048];   // x, fp16
__device__ __half g_WqT[2048 * 2048];   // Wq^T [n][k] fp16
__device__ __half g_WkT[512  * 2048];
__device__ __half g_WvT[512  * 2048];
__device__ __half g_WoT[2048 * 2048];
__device__ __half g_Qh [4096 * 2048];   // q proj, scaled, fp16 [seq][dim]
__device__ __half g_Kh [4096 * 512];    // k proj fp16 [seq][gdim]
__device__ __half g_Vt [8 * 128 * 2048];// v proj TRANSPOSED [b*g][dim][seq]
__device__ __half g_Ch [4096 * 2048];   // ctx fp16

// ---------------- helpers ----------------
__device__ __forceinline__ void mma_f16(float* d, const uint32_t* a, const uint32_t* b) {
    asm volatile(
        "mma.sync.aligned.m16n8k16.row.col.f32.f16.f16.f32 "
        "{%0,%1,%2,%3}, {%4,%5,%6,%7}, {%8,%9}, {%0,%1,%2,%3};"
        : "+f"(d[0]), "+f"(d[1]), "+f"(d[2]), "+f"(d[3])
        : "r"(a[0]), "r"(a[1]), "r"(a[2]), "r"(a[3]), "r"(b[0]), "r"(b[1]));
}
__device__ __forceinline__ uint32_t smem_u32(const void* p) {
    uint32_t a;
    asm("{ .reg .u64 t; cvta.to.shared.u64 t, %1; cvt.u32.u64 %0, t; }" : "=r"(a) : "l"(p));
    return a;
}
__device__ __forceinline__ uint32_t packh2(float x, float y) {
    __half2 h = __floats2half2_rn(x, y);
    return *(uint32_t*)&h;
}
#define CP_ASYNC16(dst, src) \
    asm volatile("cp.async.cg.shared.global [%0], [%1], 16;" :: "r"(dst), "l"(src) : "memory")
#define CP_COMMIT() asm volatile("cp.async.commit_group;" ::: "memory")
#define CP_WAIT0()  asm volatile("cp.async.wait_group 0;" ::: "memory")

#define SCALE 0.08838834764831845f   /* 1/sqrt(128) */

// ---------------- prepass ----------------
__global__ void cvt_x(const float* __restrict__ in, __half* __restrict__ out) {
    size_t i = ((size_t)blockIdx.x * blockDim.x + threadIdx.x) * 4;
    float4 v = *(const float4*)(in + i);
    uint2 o;
    o.x = packh2(v.x, v.y);
    o.y = packh2(v.z, v.w);
    *(uint2*)(out + i) = o;
}

// W [K][N] fp32 -> Wt [N][K] fp16
__global__ void transpose_h(const float* __restrict__ W, __half* __restrict__ Wt,
                            int K, int N) {
    __shared__ float t[32][33];
    int x = blockIdx.x * 32 + threadIdx.x;   // n
    int y = blockIdx.y * 32 + threadIdx.y;   // k
#pragma unroll
    for (int i = 0; i < 32; i += 8)
        t[threadIdx.y + i][threadIdx.x] = W[(size_t)(y + i) * N + x];
    __syncthreads();
    int x2 = blockIdx.y * 32 + threadIdx.x;  // k
    int y2 = blockIdx.x * 32 + threadIdx.y;  // n
#pragma unroll
    for (int i = 0; i < 32; i += 8)
        Wt[(size_t)(y2 + i) * K + x2] = __float2half_rn(t[threadIdx.x][threadIdx.y + i]);
}

// ------- fp16 mma GEMM: CTA 128x256, 8 warps @ 64x64, BK=128, 2-stage -------
#define HLD 136                          /* half row stride */
#define AS_B (128 * 272)                 /* 34816 B */
#define BS_B (256 * 272)                 /* 69632 B */
#define STG_B (AS_B + BS_B)              /* 104448 B */
#define GEMM_SMEM (2 * STG_B)            /* 208896 B */

template <bool PROJ>
__global__ __launch_bounds__(256, 1) void gemm_h(
    const __half* __restrict__ A,
    const __half* __restrict__ B0, const __half* __restrict__ B1,
    const __half* __restrict__ B2,
    __half* __restrict__ Qo, __half* __restrict__ Ko, __half* __restrict__ Vo,
    float* __restrict__ Co, const float* __restrict__ bias)
{
    extern __shared__ char smc[];
    const int tid = threadIdx.x;
    const int wid = tid >> 5, l = tid & 31;
    const int lq = l >> 2, lr = l & 3;
    const int m0 = blockIdx.y * 128;
    const int n0 = blockIdx.x * 256;
    const int wm = (wid & 1) * 64, wn = (wid >> 1) * 64;
    const uint32_t smb = smem_u32(smc);

    const __half* Bp;
    if (PROJ) {
        if (n0 < 2048)      Bp = B0 + (size_t)n0 * GK;
        else if (n0 < 2560) Bp = B1 + (size_t)(n0 - 2048) * GK;
        else                Bp = B2 + (size_t)(n0 - 2560) * GK;
    } else Bp = B0 + (size_t)n0 * GK;

    float acc[4][8][4];
#pragma unroll
    for (int i = 0; i < 4; i++)
#pragma unroll
        for (int j = 0; j < 8; j++)
#pragma unroll
            for (int r = 0; r < 4; r++) acc[i][j][r] = 0.f;

    // A: 128 rows x 16 chunks = 2048 -> 8/thread. B: 256 x 16 = 4096 -> 16/thread.
#define G_LOAD(s, kc) do {                                                        \
        uint32_t _ab = smb + (s) * STG_B;                                         \
        uint32_t _bb = _ab + AS_B;                                                \
        _Pragma("unroll")                                                         \
        for (int _i = 0; _i < 8; _i++) {                                          \
            int _e = tid + _i * 256, _r = _e >> 4, _ch = _e & 15;                 \
            CP_ASYNC16(_ab + _r * 272 + _ch * 16,                                 \
                (const void*)(A + (size_t)(m0 + _r) * GK + (kc) * 128 + _ch * 8));\
        }                                                                         \
        _Pragma("unroll")                                                         \
        for (int _i = 0; _i < 16; _i++) {                                         \
            int _e = tid + _i * 256, _r = _e >> 4, _ch = _e & 15;                 \
            CP_ASYNC16(_bb + _r * 272 + _ch * 16,                                 \
                (const void*)(Bp + (size_t)_r * GK + (kc) * 128 + _ch * 8));      \
        }                                                                         \
    } while (0)

    G_LOAD(0, 0); CP_COMMIT();

    for (int it = 0; it < 16; it++) {
        CP_WAIT0();
        __syncthreads();
        if (it + 1 < 16) { G_LOAD((it + 1) & 1, it + 1); CP_COMMIT(); }

        const __half* As = (const __half*)(smc + (it & 1) * STG_B);
        const __half* Bs = As + 128 * HLD;

#pragma unroll
        for (int ks = 0; ks < 8; ks++) {
            uint32_t af[4][4], bf[8][2];
#pragma unroll
            for (int mf = 0; mf < 4; mf++) {
                const __half* p = As + (wm + mf * 16 + lq) * HLD + ks * 16 + 2 * lr;
                af[mf][0] = *(const uint32_t*)(p);
                af[mf][1] = *(const uint32_t*)(p + 8 * HLD);
                af[mf][2] = *(const uint32_t*)(p + 8);
                af[mf][3] = *(const uint32_t*)(p + 8 * HLD + 8);
            }
#pragma unroll
            for (int nf = 0; nf < 8; nf++) {
                const __half* p = Bs + (wn + nf * 8 + lq) * HLD + ks * 16 + 2 * lr;
                bf[nf][0] = *(const uint32_t*)(p);
                bf[nf][1] = *(const uint32_t*)(p + 8);
            }
#pragma unroll
            for (int mf = 0; mf < 4; mf++)
#pragma unroll
                for (int nf = 0; nf < 8; nf++)
                    mma_f16(acc[mf][nf], af[mf], bf[nf]);
        }
    }

    // epilogue
#pragma unroll
    for (int mf = 0; mf < 4; mf++) {
        const int row = m0 + wm + mf * 16 + lq;
#pragma unroll
        for (int nf = 0; nf < 8; nf++) {
            const int col = wn + nf * 8 + 2 * lr;
            const float c0 = acc[mf][nf][0], c1 = acc[mf][nf][1];
            const float c2 = acc[mf][nf][2], c3 = acc[mf][nf][3];
            if (!PROJ) {
                float2 b = *(const float2*)(bias + n0 + col);
                *(float2*)(Co + (size_t)row * 2048 + n0 + col) =
                    make_float2(c0 + b.x, c1 + b.y);
                *(float2*)(Co + (size_t)(row + 8) * 2048 + n0 + col) =
                    make_float2(c2 + b.x, c3 + b.y);
            } else if (n0 < 2048) {
                *(uint32_t*)(Qo + (size_t)row * 2048 + n0 + col) =
                    packh2(c0 * SCALE, c1 * SCALE);
                *(uint32_t*)(Qo + (size_t)(row + 8) * 2048 + n0 + col) =
                    packh2(c2 * SCALE, c3 * SCALE);
            } else if (n0 < 2560) {
                const int kc = n0 - 2048 + col;
                *(uint32_t*)(Ko + (size_t)row * 512 + kc) = packh2(c0, c1);
                *(uint32_t*)(Ko + (size_t)(row + 8) * 512 + kc) = packh2(c2, c3);
            } else {
                const int vd = n0 - 2560 + col;
                const int gi = vd >> 7, d = vd & 127;
                const int bi = row >> 11, s = row & 2047;
                __half* vb = Vo + ((size_t)(bi * NG + gi) * 128 + d) * 2048;
                vb[s]            = __float2half_rn(c0);
                vb[2048 + s]     = __float2half_rn(c1);
                vb[s + 8]        = __float2half_rn(c2);
                vb[2048 + s + 8] = __float2half_rn(c3);
            }
        }
    }
#undef G_LOAD
}

// -------- fp16 mma flash-attention: split-softmax 4x2 warps, 128-key tiles --
// smem: Q [128][136]h | K stages 2x[128 keys][136]h | Vt stages 2x[128 dims][136]h
#define QS_B (128 * 272)
#define KS_B (128 * 272)
#define VS_B (128 * 272)
#define ATTN_SMEM (QS_B + 2 * KS_B + 2 * VS_B)   /* 174080 B */

__global__ __launch_bounds__(256, 1) void attn_h(
    const __half* __restrict__ Q, const __half* __restrict__ K,
    const __half* __restrict__ VT, __half* __restrict__ C)
{
    extern __shared__ char smc[];
    const int tid = threadIdx.x;
    const int wid = tid >> 5, l = tid & 31;
    const int lq = l >> 2, lr = l & 3;
    const int wr = wid >> 1, wc = wid & 1;
    const int wq = wr * 32;
    const int koff = wc * 64;

    const int qc = gridDim.x - 1 - blockIdx.x;   // long CTAs first
    const int hh = blockIdx.y;
    const int bi = hh >> 4;
    const int gi = (hh >> 2) & 3;
    const int hi = hh & 3;
    const int qcol = (gi * HPG + hi) * HD;
    const int kcol = gi * HD;
    const size_t rowbase = (size_t)bi * SEQ;
    const int qbase = qc * 128;
    const uint32_t smb = smem_u32(smc);
    const __half* vtb = VT + (size_t)(bi * NG + gi) * 128 * 2048;

    // ---- Q tile [128 q][128 d] fp16 ----
#pragma unroll
    for (int u = 0; u < 8; u++) {
        int e = tid + u * 256, r = e >> 4, ch = e & 15;
        CP_ASYNC16(smb + r * 272 + ch * 16,
                   (const void*)(Q + (rowbase + qbase + r) * 2048 + qcol + ch * 8));
    }

    float o[2][16][4];
#pragma unroll
    for (int mf = 0; mf < 2; mf++)
#pragma unroll
        for (int i = 0; i < 16; i++)
#pragma unroll
            for (int r = 0; r < 4; r++) o[mf][i][r] = 0.f;
    float mm[2][2], ll[2][2];
#pragma unroll
    for (int mf = 0; mf < 2; mf++) {
        mm[mf][0] = -CUDART_INF_F; mm[mf][1] = -CUDART_INF_F;
        ll[mf][0] = 0.f; ll[mf][1] = 0.f;
    }

    const int jmax = qc;

#define KV_LOAD(ss, jj) do {                                                     \
        uint32_t _kb = smb + QS_B + (ss) * KS_B;                                  \
        uint32_t _vb = smb + QS_B + 2 * KS_B + (ss) * VS_B;                       \
        _Pragma("unroll")                                                         \
        for (int _u = 0; _u < 8; _u++) {                                          \
            int _e = tid + _u * 256, _r = _e >> 4, _ch = _e & 15;                 \
            CP_ASYNC16(_kb + _r * 272 + _ch * 16,                                 \
                (const void*)(K + (rowbase + (jj) * 128 + _r) * 512 + kcol + _ch * 8)); \
            CP_ASYNC16(_vb + _r * 272 + _ch * 16,                                 \
                (const void*)(vtb + (size_t)_r * 2048 + (jj) * 128 + _ch * 8));   \
        }                                                                         \
    } while (0)

    KV_LOAD(0, 0); CP_COMMIT();

    for (int j = 0; j <= jmax; j++) {
        CP_WAIT0();
        __syncthreads();
        if (j < jmax) { KV_LOAD((j + 1) & 1, j + 1); CP_COMMIT(); }

        const int st = j & 1;
        const __half* Qs = (const __half*)smc;
        const __half* Ks = (const __half*)(smc + QS_B + st * KS_B);
        const __half* Vs = (const __half*)(smc + QS_B + 2 * KS_B + st * VS_B);
        const int kb = j * 128 + koff;            // warp's first key
        if (kb > qbase + wq + 31) continue;       // warp half fully masked

        // ---- S = Q @ K^T : 32 q x 64 keys (fp16 MMA, fp32 acc) ----
        float s_[2][8][4];
#pragma unroll
        for (int mf = 0; mf < 2; mf++)
#pragma unroll
            for (int nf = 0; nf < 8; nf++)
#pragma unroll
                for (int r = 0; r < 4; r++) s_[mf][nf][r] = 0.f;

#pragma unroll
        for (int kf = 0; kf < 8; kf++) {
            uint32_t qa[2][4];
#pragma unroll
            for (int mf = 0; mf < 2; mf++) {
                const __half* qp = Qs + (wq + mf * 16 + lq) * HLD + kf * 16 + 2 * lr;
                qa[mf][0] = *(const uint32_t*)(qp);
                qa[mf][1] = *(const uint32_t*)(qp + 8 * HLD);
                qa[mf][2] = *(const uint32_t*)(qp + 8);
                qa[mf][3] = *(const uint32_t*)(qp + 8 * HLD + 8);
            }
#pragma unroll
            for (int nf = 0; nf < 8; nf++) {
                const __half* kp = Ks + (koff + nf * 8 + lq) * HLD + kf * 16 + 2 * lr;
                uint32_t b[2] = { *(const uint32_t*)(kp), *(const uint32_t*)(kp + 8) };
                mma_f16(s_[0][nf], qa[0], b);
                mma_f16(s_[1][nf], qa[1], b);
            }
        }

        // ---- per-warp softmax over its 64-key half ----
        const bool needmask = (kb + 63 > qbase + wq);
        uint32_t P2[2][4][4];
#pragma unroll
        for (int mf = 0; mf < 2; mf++) {
            const int gr0 = qbase + wq + mf * 16 + lq;
            const int gr1 = gr0 + 8;
            float mx0 = -CUDART_INF_F, mx1 = -CUDART_INF_F;
#pragma unroll
            for (int nf = 0; nf < 8; nf++) {
                if (needmask) {
                    const int c0 = kb + nf * 8 + 2 * lr;
                    if (c0 > gr0)     s_[mf][nf][0] = -CUDART_INF_F;
                    if (c0 + 1 > gr0) s_[mf][nf][1] = -CUDART_INF_F;
                    if (c0 > gr1)     s_[mf][nf][2] = -CUDART_INF_F;
                    if (c0 + 1 > gr1) s_[mf][nf][3] = -CUDART_INF_F;
                }
                mx0 = fmaxf(mx0, fmaxf(s_[mf][nf][0], s_[mf][nf][1]));
                mx1 = fmaxf(mx1, fmaxf(s_[mf][nf][2], s_[mf][nf][3]));
            }
#pragma unroll
            for (int msk = 1; msk < 4; msk <<= 1) {
                mx0 = fmaxf(mx0, __shfl_xor_sync(0xffffffffu, mx0, msk));
                mx1 = fmaxf(mx1, __shfl_xor_sync(0xffffffffu, mx1, msk));
            }
            const float nm0 = fmaxf(mm[mf][0], mx0);
            const float nm1 = fmaxf(mm[mf][1], mx1);
            const float al0 = __expf(mm[mf][0] - nm0);
            const float al1 = __expf(mm[mf][1] - nm1);
            mm[mf][0] = nm0; mm[mf][1] = nm1;

            float sm0 = 0.f, sm1 = 0.f;
#pragma unroll
            for (int nf = 0; nf < 8; nf++) {
                float p0 = __expf(s_[mf][nf][0] - nm0);
                float p1 = __expf(s_[mf][nf][1] - nm0);
                float p2 = __expf(s_[mf][nf][2] - nm1);
                float p3 = __expf(s_[mf][nf][3] - nm1);
                sm0 += p0 + p1; sm1 += p2 + p3;
                s_[mf][nf][0] = p0; s_[mf][nf][1] = p1;
                s_[mf][nf][2] = p2; s_[mf][nf][3] = p3;
            }
#pragma unroll
            for (int msk = 1; msk < 4; msk <<= 1) {
                sm0 += __shfl_xor_sync(0xffffffffu, sm0, msk);
                sm1 += __shfl_xor_sync(0xffffffffu, sm1, msk);
            }
            ll[mf][0] = ll[mf][0] * al0 + sm0;
            ll[mf][1] = ll[mf][1] * al1 + sm1;
#pragma unroll
            for (int nf = 0; nf < 16; nf++) {
                o[mf][nf][0] *= al0; o[mf][nf][1] *= al0;
                o[mf][nf][2] *= al1; o[mf][nf][3] *= al1;
            }
            // pack P c-frags directly into fp16 a-frags (no shuffle, no smem)
#pragma unroll
            for (int kf = 0; kf < 4; kf++) {
                P2[mf][kf][0] = packh2(s_[mf][2 * kf][0],     s_[mf][2 * kf][1]);
                P2[mf][kf][1] = packh2(s_[mf][2 * kf][2],     s_[mf][2 * kf][3]);
                P2[mf][kf][2] = packh2(s_[mf][2 * kf + 1][0], s_[mf][2 * kf + 1][1]);
                P2[mf][kf][3] = packh2(s_[mf][2 * kf + 1][2], s_[mf][2 * kf + 1][3]);
            }
        }

        // ---- O += P @ V : V^T smem rows = dims, b-frags contiguous ----
#pragma unroll
        for (int kf = 0; kf < 4; kf++) {
#pragma unroll
            for (int nf = 0; nf < 16; nf++) {
                const __half* vp = Vs + (nf * 8 + lq) * HLD + koff + kf * 16 + 2 * lr;
                uint32_t b[2] = { *(const uint32_t*)(vp), *(const uint32_t*)(vp + 8) };
                mma_f16(o[0][nf], P2[0][kf], b);
                mma_f16(o[1][nf], P2[1][kf], b);
            }
        }
    }

    // ---- merge key-halves: wc=1 publishes (fp32), wc=0 combines + stores ----
    float* Ox = (float*)smc;                 // [4][32][132] fp32
    float* St = Ox + 4 * 32 * 132;           // [128][2]
    __syncthreads();
    if (wc == 1) {
        float* ob = Ox + wr * 32 * 132;
#pragma unroll
        for (int mf = 0; mf < 2; mf++) {
            const int row0 = mf * 16 + lq;
#pragma unroll
            for (int nf = 0; nf < 16; nf++) {
                const int col = nf * 8 + 2 * lr;
                *(float2*)&ob[row0 * 132 + col]       = make_float2(o[mf][nf][0], o[mf][nf][1]);
                *(float2*)&ob[(row0 + 8) * 132 + col] = make_float2(o[mf][nf][2], o[mf][nf][3]);
            }
            if (lr == 0) {
                float* st = St + (wr * 32 + row0) * 2;
                st[0] = mm[mf][0]; st[1] = ll[mf][0];
                st[16] = mm[mf][1]; st[17] = ll[mf][1];
            }
        }
    }
    __syncthreads();
    if (wc == 0) {
        const float* ob = Ox + wr * 32 * 132;
#pragma unroll
        for (int mf = 0; mf < 2; mf++) {
            const int row0 = mf * 16 + lq;
            const float* st = St + (wr * 32 + row0) * 2;
            const float mo0 = st[0],  lo0 = st[1];
            const float mo1 = st[16], lo1 = st[17];
            const float M0 = fmaxf(mm[mf][0], mo0);
            const float M1 = fmaxf(mm[mf][1], mo1);
            const float as0 = __expf(mm[mf][0] - M0), ao0 = __expf(mo0 - M0);
            const float as1 = __expf(mm[mf][1] - M1), ao1 = __expf(mo1 - M1);
            const float inv0 = 1.f / (ll[mf][0] * as0 + lo0 * ao0);
            const float inv1 = 1.f / (ll[mf][1] * as1 + lo1 * ao1);
            const float fs0 = as0 * inv0, fo0 = ao0 * inv0;
            const float fs1 = as1 * inv1, fo1 = ao1 * inv1;
            const size_t r0 = rowbase + qbase + wq + row0;
            const size_t r1 = r0 + 8;
#pragma unroll
            for (int nf = 0; nf < 16; nf++) {
                const int col = nf * 8 + 2 * lr;
                float2 q0 = *(const float2*)&ob[row0 * 132 + col];
                float2 q1 = *(const float2*)&ob[(row0 + 8) * 132 + col];
                *(uint32_t*)(C + r0 * 2048 + qcol + col) =
                    packh2(o[mf][nf][0] * fs0 + q0.x * fo0,
                           o[mf][nf][1] * fs0 + q0.y * fo0);
                *(uint32_t*)(C + r1 * 2048 + qcol + col) =
                    packh2(o[mf][nf][2] * fs1 + q1.x * fo1,
                           o[mf][nf][3] * fs1 + q1.y * fo1);
            }
        }
    }
#undef KV_LOAD
}

// ---------------------------------------------------------------------------
extern "C" void kernel_launch(void* const* d_in, const int* in_sizes, int n_in,
                              void* d_out, int out_size)
{
    const float* x  = (const float*)d_in[0];
    const float* Wq = (const float*)d_in[1];
    const float* Wk = (const float*)d_in[2];
    const float* Wv = (const float*)d_in[3];
    const float* Wo = (const float*)d_in[4];
    const float* bo = (const float*)d_in[5];

    const int M = in_sizes[0] / D_IN;   // 4096
    const int B = M / SEQ;              // 2

    __half *Xh, *WqT, *WkT, *WvT, *WoT, *Qh, *Kh, *Vt, *Ch;
    cudaGetSymbolAddress((void**)&Xh,  g_Xh);
    cudaGetSymbolAddress((void**)&WqT, g_WqT);
    cudaGetSymbolAddress((void**)&WkT, g_WkT);
    cudaGetSymbolAddress((void**)&WvT, g_WvT);
    cudaGetSymbolAddress((void**)&WoT, g_WoT);
    cudaGetSymbolAddress((void**)&Qh,  g_Qh);
    cudaGetSymbolAddress((void**)&Kh,  g_Kh);
    cudaGetSymbolAddress((void**)&Vt,  g_Vt);
    cudaGetSymbolAddress((void**)&Ch,  g_Ch);

    cudaFuncSetAttribute(gemm_h<true>,
                         cudaFuncAttributeMaxDynamicSharedMemorySize, GEMM_SMEM);
    cudaFuncSetAttribute(gemm_h<false>,
                         cudaFuncAttributeMaxDynamicSharedMemorySize, GEMM_SMEM);
    cudaFuncSetAttribute(attn_h,
                         cudaFuncAttributeMaxDynamicSharedMemorySize, ATTN_SMEM);

    // prepass: fp16 conversions (+ weight transposes to [n][k])
    cvt_x<<<(M * D_IN) / 1024, 256>>>(x, Xh);
    transpose_h<<<dim3(64, 64), dim3(32, 8)>>>(Wq, WqT, 2048, 2048);
    transpose_h<<<dim3(16, 64), dim3(32, 8)>>>(Wk, WkT, 2048, 512);
    transpose_h<<<dim3(16, 64), dim3(32, 8)>>>(Wv, WvT, 2048, 512);
    transpose_h<<<dim3(64, 64), dim3(32, 8)>>>(Wo, WoT, 2048, 2048);

    // fused QKV projection: N = 2048 (Q) + 512 (K) + 512 (V^T) = 3072
    gemm_h<true><<<dim3(12, M / 128), 256, GEMM_SMEM>>>(
        Xh, WqT, WkT, WvT, Qh, Kh, Vt, nullptr, nullptr);

    attn_h<<<dim3(SEQ / 128, B * 16), 256, ATTN_SMEM>>>(Qh, Kh, Vt, Ch);

    // output projection + bias (fp32 out)
    gemm_h<false><<<dim3(8, M / 128), 256, GEMM_SMEM>>>(
        Ch, WoT, nullptr, nullptr, nullptr, nullptr, nullptr, (float*)d_out, bo);
}

// round 9
// speedup vs baseline: 2.2325x; 1.0129x over previous
#include <cuda_runtime.h>
#include <cuda_fp16.h>
#include <math_constants.h>
#include <cstdint>

#define D_IN   2048
#define D_OUT  2048
#define HD     128
#define NG     4
#define HPG    4
#define SEQ    2048
#define GK     2048      /* K dim of every GEMM */

// ---------------- scratch (no cudaMalloc allowed) ----------------
__device__ __half g_Xh [4096 * 2048];   // x, fp16
__device__ __half g_WqT[2048 * 2048];   // Wq^T [n][k] fp16
__device__ __half g_WkT[512  * 2048];
__device__ __half g_WvT[512  * 2048];
__device__ __half g_WoT[2048 * 2048];
__device__ __half g_Qh [4096 * 2048];   // q proj, scaled, fp16 [seq][dim]
__device__ __half g_Kh [4096 * 512];    // k proj fp16 [seq][gdim]
__device__ __half g_Vt [8 * 128 * 2048];// v proj TRANSPOSED [b*g][dim][seq]
__device__ __half g_Ch [4096 * 2048];   // ctx fp16

// ---------------- helpers ----------------
__device__ __forceinline__ void mma_f16(float* d, const uint32_t* a, const uint32_t* b) {
    asm volatile(
        "mma.sync.aligned.m16n8k16.row.col.f32.f16.f16.f32 "
        "{%0,%1,%2,%3}, {%4,%5,%6,%7}, {%8,%9}, {%0,%1,%2,%3};"
        : "+f"(d[0]), "+f"(d[1]), "+f"(d[2]), "+f"(d[3])
        : "r"(a[0]), "r"(a[1]), "r"(a[2]), "r"(a[3]), "r"(b[0]), "r"(b[1]));
}
__device__ __forceinline__ uint32_t smem_u32(const void* p) {
    uint32_t a;
    asm("{ .reg .u64 t; cvta.to.shared.u64 t, %1; cvt.u32.u64 %0, t; }" : "=r"(a) : "l"(p));
    return a;
}
__device__ __forceinline__ uint32_t packh2(float x, float y) {
    __half2 h = __floats2half2_rn(x, y);
    return *(uint32_t*)&h;
}
#define LDSM_X4(r0, r1, r2, r3, addr) \
    asm volatile("ldmatrix.sync.aligned.m8n8.x4.shared.b16 {%0,%1,%2,%3}, [%4];" \
        : "=r"(r0), "=r"(r1), "=r"(r2), "=r"(r3) : "r"(addr))
#define CP_ASYNC16(dst, src) \
    asm volatile("cp.async.cg.shared.global [%0], [%1], 16;" :: "r"(dst), "l"(src) : "memory")
#define CP_COMMIT() asm volatile("cp.async.commit_group;" ::: "memory")
#define CP_WAIT0()  asm volatile("cp.async.wait_group 0;" ::: "memory")

#define SCALE 0.08838834764831845f   /* 1/sqrt(128) */

// ---------------- prepass ----------------
__global__ void cvt_x(const float* __restrict__ in, __half* __restrict__ out) {
    size_t i = ((size_t)blockIdx.x * blockDim.x + threadIdx.x) * 4;
    float4 v = *(const float4*)(in + i);
    uint2 o;
    o.x = packh2(v.x, v.y);
    o.y = packh2(v.z, v.w);
    *(uint2*)(out + i) = o;
}

// W [K][N] fp32 -> Wt [N][K] fp16
__global__ void transpose_h(const float* __restrict__ W, __half* __restrict__ Wt,
                            int K, int N) {
    __shared__ float t[32][33];
    int x = blockIdx.x * 32 + threadIdx.x;   // n
    int y = blockIdx.y * 32 + threadIdx.y;   // k
#pragma unroll
    for (int i = 0; i < 32; i += 8)
        t[threadIdx.y + i][threadIdx.x] = W[(size_t)(y + i) * N + x];
    __syncthreads();
    int x2 = blockIdx.y * 32 + threadIdx.x;  // k
    int y2 = blockIdx.x * 32 + threadIdx.y;  // n
#pragma unroll
    for (int i = 0; i < 32; i += 8)
        Wt[(size_t)(y2 + i) * K + x2] = __float2half_rn(t[threadIdx.x][threadIdx.y + i]);
}

// ------- fp16 mma GEMM: CTA 128x256, 8 warps @ 64x64, BK=128, 2-stage -------
// All fragment loads via ldmatrix.x4.
#define HLD 136                          /* half row stride (272 B) */
#define AS_B (128 * 272)
#define BS_B (256 * 272)
#define STG_B (AS_B + BS_B)
#define GEMM_SMEM (2 * STG_B)            /* 208896 B */

template <bool PROJ>
__global__ __launch_bounds__(256, 1) void gemm_h(
    const __half* __restrict__ A,
    const __half* __restrict__ B0, const __half* __restrict__ B1,
    const __half* __restrict__ B2,
    __half* __restrict__ Qo, __half* __restrict__ Ko, __half* __restrict__ Vo,
    float* __restrict__ Co, const float* __restrict__ bias)
{
    extern __shared__ char smc[];
    const int tid = threadIdx.x;
    const int wid = tid >> 5, l = tid & 31;
    const int lq = l >> 2, lr = l & 3;
    const int m0 = blockIdx.y * 128;
    const int n0 = blockIdx.x * 256;
    const int wm = (wid & 1) * 64, wn = (wid >> 1) * 64;
    const uint32_t smb = smem_u32(smc);

    const __half* Bp;
    if (PROJ) {
        if (n0 < 2048)      Bp = B0 + (size_t)n0 * GK;
        else if (n0 < 2560) Bp = B1 + (size_t)(n0 - 2048) * GK;
        else                Bp = B2 + (size_t)(n0 - 2560) * GK;
    } else Bp = B0 + (size_t)n0 * GK;

    float acc[4][8][4];
#pragma unroll
    for (int i = 0; i < 4; i++)
#pragma unroll
        for (int j = 0; j < 8; j++)
#pragma unroll
            for (int r = 0; r < 4; r++) acc[i][j][r] = 0.f;

    // ldmatrix lane-address components
    const uint32_t a_lane = (uint32_t)((wm + (l & 15)) * 272 + (l >> 4) * 16);
    const uint32_t b_lane = (uint32_t)((wn + (l & 7) + ((l >> 4) << 3)) * 272
                                       + ((l >> 3) & 1) * 16);

#define G_LOAD(s, kc) do {                                                        \
        uint32_t _ab = smb + (s) * STG_B;                                         \
        uint32_t _bb = _ab + AS_B;                                                \
        _Pragma("unroll")                                                         \
        for (int _i = 0; _i < 8; _i++) {                                          \
            int _e = tid + _i * 256, _r = _e >> 4, _ch = _e & 15;                 \
            CP_ASYNC16(_ab + _r * 272 + _ch * 16,                                 \
                (const void*)(A + (size_t)(m0 + _r) * GK + (kc) * 128 + _ch * 8));\
        }                                                                         \
        _Pragma("unroll")                                                         \
        for (int _i = 0; _i < 16; _i++) {                                         \
            int _e = tid + _i * 256, _r = _e >> 4, _ch = _e & 15;                 \
            CP_ASYNC16(_bb + _r * 272 + _ch * 16,                                 \
                (const void*)(Bp + (size_t)_r * GK + (kc) * 128 + _ch * 8));      \
        }                                                                         \
    } while (0)

    G_LOAD(0, 0); CP_COMMIT();

    for (int it = 0; it < 16; it++) {
        CP_WAIT0();
        __syncthreads();
        if (it + 1 < 16) { G_LOAD((it + 1) & 1, it + 1); CP_COMMIT(); }

        const uint32_t abase = smb + (it & 1) * STG_B + a_lane;
        const uint32_t bbase = smb + (it & 1) * STG_B + AS_B + b_lane;

#pragma unroll
        for (int ks = 0; ks < 8; ks++) {
            uint32_t af[4][4], bf[8][2];
#pragma unroll
            for (int mf = 0; mf < 4; mf++)
                LDSM_X4(af[mf][0], af[mf][1], af[mf][2], af[mf][3],
                        abase + mf * (16 * 272) + ks * 32);
#pragma unroll
            for (int p = 0; p < 4; p++)
                LDSM_X4(bf[2 * p][0], bf[2 * p][1], bf[2 * p + 1][0], bf[2 * p + 1][1],
                        bbase + p * (16 * 272) + ks * 32);
#pragma unroll
            for (int mf = 0; mf < 4; mf++)
#pragma unroll
                for (int nf = 0; nf < 8; nf++)
                    mma_f16(acc[mf][nf], af[mf], bf[nf]);
        }
    }

    // epilogue
#pragma unroll
    for (int mf = 0; mf < 4; mf++) {
        const int row = m0 + wm + mf * 16 + lq;
#pragma unroll
        for (int nf = 0; nf < 8; nf++) {
            const int col = wn + nf * 8 + 2 * lr;
            const float c0 = acc[mf][nf][0], c1 = acc[mf][nf][1];
            const float c2 = acc[mf][nf][2], c3 = acc[mf][nf][3];
            if (!PROJ) {
                float2 b = *(const float2*)(bias + n0 + col);
                *(float2*)(Co + (size_t)row * 2048 + n0 + col) =
                    make_float2(c0 + b.x, c1 + b.y);
                *(float2*)(Co + (size_t)(row + 8) * 2048 + n0 + col) =
                    make_float2(c2 + b.x, c3 + b.y);
            } else if (n0 < 2048) {
                *(uint32_t*)(Qo + (size_t)row * 2048 + n0 + col) =
                    packh2(c0 * SCALE, c1 * SCALE);
                *(uint32_t*)(Qo + (size_t)(row + 8) * 2048 + n0 + col) =
                    packh2(c2 * SCALE, c3 * SCALE);
            } else if (n0 < 2560) {
                const int kc = n0 - 2048 + col;
                *(uint32_t*)(Ko + (size_t)row * 512 + kc) = packh2(c0, c1);
                *(uint32_t*)(Ko + (size_t)(row + 8) * 512 + kc) = packh2(c2, c3);
            } else {
                const int vd = n0 - 2560 + col;
                const int gi = vd >> 7, d = vd & 127;
                const int bi = row >> 11, s = row & 2047;
                __half* vb = Vo + ((size_t)(bi * NG + gi) * 128 + d) * 2048;
                vb[s]            = __float2half_rn(c0);
                vb[2048 + s]     = __float2half_rn(c1);
                vb[s + 8]        = __float2half_rn(c2);
                vb[2048 + s + 8] = __float2half_rn(c3);
            }
        }
    }
#undef G_LOAD
}

// -------- fp16 mma flash-attention: split-softmax 4x2 warps, 128-key tiles --
#define QS_B (128 * 272)
#define KS_B (128 * 272)
#define VS_B (128 * 272)
#define ATTN_SMEM (QS_B + 2 * KS_B + 2 * VS_B)   /* 174080 B */

__global__ __launch_bounds__(256, 1) void attn_h(
    const __half* __restrict__ Q, const __half* __restrict__ K,
    const __half* __restrict__ VT, __half* __restrict__ C)
{
    extern __shared__ char smc[];
    const int tid = threadIdx.x;
    const int wid = tid >> 5, l = tid & 31;
    const int lq = l >> 2, lr = l & 3;
    const int wr = wid >> 1, wc = wid & 1;
    const int wq = wr * 32;
    const int koff = wc * 64;

    const int qc = gridDim.x - 1 - blockIdx.x;   // long CTAs first
    const int hh = blockIdx.y;
    const int bi = hh >> 4;
    const int gi = (hh >> 2) & 3;
    const int hi = hh & 3;
    const int qcol = (gi * HPG + hi) * HD;
    const int kcol = gi * HD;
    const size_t rowbase = (size_t)bi * SEQ;
    const int qbase = qc * 128;
    const uint32_t smb = smem_u32(smc);
    const __half* vtb = VT + (size_t)(bi * NG + gi) * 128 * 2048;

    // ldmatrix lane-address components
    const uint32_t qa_lane = (uint32_t)((wq + (l & 15)) * 272 + (l >> 4) * 16);
    const uint32_t kb_lane = (uint32_t)((koff + (l & 7) + ((l >> 4) << 3)) * 272
                                        + ((l >> 3) & 1) * 16);
    const uint32_t vb_lane = (uint32_t)(((l & 7) + ((l >> 4) << 3)) * 272
                                        + ((l >> 3) & 1) * 16 + koff * 2);

    // ---- Q tile [128 q][128 d] fp16 ----
#pragma unroll
    for (int u = 0; u < 8; u++) {
        int e = tid + u * 256, r = e >> 4, ch = e & 15;
        CP_ASYNC16(smb + r * 272 + ch * 16,
                   (const void*)(Q + (rowbase + qbase + r) * 2048 + qcol + ch * 8));
    }

    float o[2][16][4];
#pragma unroll
    for (int mf = 0; mf < 2; mf++)
#pragma unroll
        for (int i = 0; i < 16; i++)
#pragma unroll
            for (int r = 0; r < 4; r++) o[mf][i][r] = 0.f;
    float mm[2][2], ll[2][2];
#pragma unroll
    for (int mf = 0; mf < 2; mf++) {
        mm[mf][0] = -CUDART_INF_F; mm[mf][1] = -CUDART_INF_F;
        ll[mf][0] = 0.f; ll[mf][1] = 0.f;
    }

    const int jmax = qc;

#define KV_LOAD(ss, jj) do {                                                     \
        uint32_t _kb = smb + QS_B + (ss) * KS_B;                                  \
        uint32_t _vb = smb + QS_B + 2 * KS_B + (ss) * VS_B;                       \
        _Pragma("unroll")                                                         \
        for (int _u = 0; _u < 8; _u++) {                                          \
            int _e = tid + _u * 256, _r = _e >> 4, _ch = _e & 15;                 \
            CP_ASYNC16(_kb + _r * 272 + _ch * 16,                                 \
                (const void*)(K + (rowbase + (jj) * 128 + _r) * 512 + kcol + _ch * 8)); \
            CP_ASYNC16(_vb + _r * 272 + _ch * 16,                                 \
                (const void*)(vtb + (size_t)_r * 2048 + (jj) * 128 + _ch * 8));   \
        }                                                                         \
    } while (0)

    KV_LOAD(0, 0); CP_COMMIT();

    for (int j = 0; j <= jmax; j++) {
        CP_WAIT0();
        __syncthreads();
        if (j < jmax) { KV_LOAD((j + 1) & 1, j + 1); CP_COMMIT(); }

        const int st = j & 1;
        const uint32_t qsb = smb;
        const uint32_t ksb = smb + QS_B + st * KS_B;
        const uint32_t vsb = smb + QS_B + 2 * KS_B + st * VS_B;
        const int kb = j * 128 + koff;            // warp's first key
        if (kb > qbase + wq + 31) continue;       // warp half fully masked

        // ---- S = Q @ K^T : 32 q x 64 keys ----
        float s_[2][8][4];
#pragma unroll
        for (int mf = 0; mf < 2; mf++)
#pragma unroll
            for (int nf = 0; nf < 8; nf++)
#pragma unroll
                for (int r = 0; r < 4; r++) s_[mf][nf][r] = 0.f;

#pragma unroll
        for (int kf = 0; kf < 8; kf++) {
            uint32_t qa[2][4], kbf[8][2];
#pragma unroll
            for (int mf = 0; mf < 2; mf++)
                LDSM_X4(qa[mf][0], qa[mf][1], qa[mf][2], qa[mf][3],
                        qsb + qa_lane + mf * (16 * 272) + kf * 32);
#pragma unroll
            for (int p = 0; p < 4; p++)
                LDSM_X4(kbf[2 * p][0], kbf[2 * p][1], kbf[2 * p + 1][0], kbf[2 * p + 1][1],
                        ksb + kb_lane + p * (16 * 272) + kf * 32);
#pragma unroll
            for (int nf = 0; nf < 8; nf++) {
                mma_f16(s_[0][nf], qa[0], kbf[nf]);
                mma_f16(s_[1][nf], qa[1], kbf[nf]);
            }
        }

        // ---- per-warp softmax over its 64-key half ----
        const bool needmask = (kb + 63 > qbase + wq);
        uint32_t P2[2][4][4];
#pragma unroll
        for (int mf = 0; mf < 2; mf++) {
            const int gr0 = qbase + wq + mf * 16 + lq;
            const int gr1 = gr0 + 8;
            float mx0 = -CUDART_INF_F, mx1 = -CUDART_INF_F;
#pragma unroll
            for (int nf = 0; nf < 8; nf++) {
                if (needmask) {
                    const int c0 = kb + nf * 8 + 2 * lr;
                    if (c0 > gr0)     s_[mf][nf][0] = -CUDART_INF_F;
                    if (c0 + 1 > gr0) s_[mf][nf][1] = -CUDART_INF_F;
                    if (c0 > gr1)     s_[mf][nf][2] = -CUDART_INF_F;
                    if (c0 + 1 > gr1) s_[mf][nf][3] = -CUDART_INF_F;
                }
                mx0 = fmaxf(mx0, fmaxf(s_[mf][nf][0], s_[mf][nf][1]));
                mx1 = fmaxf(mx1, fmaxf(s_[mf][nf][2], s_[mf][nf][3]));
            }
#pragma unroll
            for (int msk = 1; msk < 4; msk <<= 1) {
                mx0 = fmaxf(mx0, __shfl_xor_sync(0xffffffffu, mx0, msk));
                mx1 = fmaxf(mx1, __shfl_xor_sync(0xffffffffu, mx1, msk));
            }
            const float nm0 = fmaxf(mm[mf][0], mx0);
            const float nm1 = fmaxf(mm[mf][1], mx1);
            const float al0 = __expf(mm[mf][0] - nm0);
            const float al1 = __expf(mm[mf][1] - nm1);
            mm[mf][0] = nm0; mm[mf][1] = nm1;

            float sm0 = 0.f, sm1 = 0.f;
#pragma unroll
            for (int nf = 0; nf < 8; nf++) {
                float p0 = __expf(s_[mf][nf][0] - nm0);
                float p1 = __expf(s_[mf][nf][1] - nm0);
                float p2 = __expf(s_[mf][nf][2] - nm1);
                float p3 = __expf(s_[mf][nf][3] - nm1);
                sm0 += p0 + p1; sm1 += p2 + p3;
                s_[mf][nf][0] = p0; s_[mf][nf][1] = p1;
                s_[mf][nf][2] = p2; s_[mf][nf][3] = p3;
            }
#pragma unroll
            for (int msk = 1; msk < 4; msk <<= 1) {
                sm0 += __shfl_xor_sync(0xffffffffu, sm0, msk);
                sm1 += __shfl_xor_sync(0xffffffffu, sm1, msk);
            }
            ll[mf][0] = ll[mf][0] * al0 + sm0;
            ll[mf][1] = ll[mf][1] * al1 + sm1;
#pragma unroll
            for (int nf = 0; nf < 16; nf++) {
                o[mf][nf][0] *= al0; o[mf][nf][1] *= al0;
                o[mf][nf][2] *= al1; o[mf][nf][3] *= al1;
            }
            // pack P c-frags directly into fp16 a-frags
#pragma unroll
            for (int kf = 0; kf < 4; kf++) {
                P2[mf][kf][0] = packh2(s_[mf][2 * kf][0],     s_[mf][2 * kf][1]);
                P2[mf][kf][1] = packh2(s_[mf][2 * kf][2],     s_[mf][2 * kf][3]);
                P2[mf][kf][2] = packh2(s_[mf][2 * kf + 1][0], s_[mf][2 * kf + 1][1]);
                P2[mf][kf][3] = packh2(s_[mf][2 * kf + 1][2], s_[mf][2 * kf + 1][3]);
            }
        }

        // ---- O += P @ V ----
#pragma unroll
        for (int kf = 0; kf < 4; kf++) {
            uint32_t vbf[16][2];
#pragma unroll
            for (int p = 0; p < 8; p++)
                LDSM_X4(vbf[2 * p][0], vbf[2 * p][1], vbf[2 * p + 1][0], vbf[2 * p + 1][1],
                        vsb + vb_lane + p * (16 * 272) + kf * 32);
#pragma unroll
            for (int nf = 0; nf < 16; nf++) {
                mma_f16(o[0][nf], P2[0][kf], vbf[nf]);
                mma_f16(o[1][nf], P2[1][kf], vbf[nf]);
            }
        }
    }

    // ---- merge key-halves: wc=1 publishes (fp32), wc=0 combines + stores ----
    float* Ox = (float*)smc;                 // [4][32][132] fp32
    float* St = Ox + 4 * 32 * 132;           // [128][2]
    __syncthreads();
    if (wc == 1) {
        float* ob = Ox + wr * 32 * 132;
#pragma unroll
        for (int mf = 0; mf < 2; mf++) {
            const int row0 = mf * 16 + lq;
#pragma unroll
            for (int nf = 0; nf < 16; nf++) {
                const int col = nf * 8 + 2 * lr;
                *(float2*)&ob[row0 * 132 + col]       = make_float2(o[mf][nf][0], o[mf][nf][1]);
                *(float2*)&ob[(row0 + 8) * 132 + col] = make_float2(o[mf][nf][2], o[mf][nf][3]);
            }
            if (lr == 0) {
                float* st = St + (wr * 32 + row0) * 2;
                st[0] = mm[mf][0]; st[1] = ll[mf][0];
                st[16] = mm[mf][1]; st[17] = ll[mf][1];
            }
        }
    }
    __syncthreads();
    if (wc == 0) {
        const float* ob = Ox + wr * 32 * 132;
#pragma unroll
        for (int mf = 0; mf < 2; mf++) {
            const int row0 = mf * 16 + lq;
            const float* st = St + (wr * 32 + row0) * 2;
            const float mo0 = st[0],  lo0 = st[1];
            const float mo1 = st[16], lo1 = st[17];
            const float M0 = fmaxf(mm[mf][0], mo0);
            const float M1 = fmaxf(mm[mf][1], mo1);
            const float as0 = __expf(mm[mf][0] - M0), ao0 = __expf(mo0 - M0);
            const float as1 = __expf(mm[mf][1] - M1), ao1 = __expf(mo1 - M1);
            const float inv0 = 1.f / (ll[mf][0] * as0 + lo0 * ao0);
            const float inv1 = 1.f / (ll[mf][1] * as1 + lo1 * ao1);
            const float fs0 = as0 * inv0, fo0 = ao0 * inv0;
            const float fs1 = as1 * inv1, fo1 = ao1 * inv1;
            const size_t r0 = rowbase + qbase + wq + row0;
            const size_t r1 = r0 + 8;
#pragma unroll
            for (int nf = 0; nf < 16; nf++) {
                const int col = nf * 8 + 2 * lr;
                float2 q0 = *(const float2*)&ob[row0 * 132 + col];
                float2 q1 = *(const float2*)&ob[(row0 + 8) * 132 + col];
                *(uint32_t*)(C + r0 * 2048 + qcol + col) =
                    packh2(o[mf][nf][0] * fs0 + q0.x * fo0,
                           o[mf][nf][1] * fs0 + q0.y * fo0);
                *(uint32_t*)(C + r1 * 2048 + qcol + col) =
                    packh2(o[mf][nf][2] * fs1 + q1.x * fo1,
                           o[mf][nf][3] * fs1 + q1.y * fo1);
            }
        }
    }
#undef KV_LOAD
}

// ---------------------------------------------------------------------------
extern "C" void kernel_launch(void* const* d_in, const int* in_sizes, int n_in,
                              void* d_out, int out_size)
{
    const float* x  = (const float*)d_in[0];
    const float* Wq = (const float*)d_in[1];
    const float* Wk = (const float*)d_in[2];
    const float* Wv = (const float*)d_in[3];
    const float* Wo = (const float*)d_in[4];
    const float* bo = (const float*)d_in[5];

    const int M = in_sizes[0] / D_IN;   // 4096
    const int B = M / SEQ;              // 2

    __half *Xh, *WqT, *WkT, *WvT, *WoT, *Qh, *Kh, *Vt, *Ch;
    cudaGetSymbolAddress((void**)&Xh,  g_Xh);
    cudaGetSymbolAddress((void**)&WqT, g_WqT);
    cudaGetSymbolAddress((void**)&WkT, g_WkT);
    cudaGetSymbolAddress((void**)&WvT, g_WvT);
    cudaGetSymbolAddress((void**)&WoT, g_WoT);
    cudaGetSymbolAddress((void**)&Qh,  g_Qh);
    cudaGetSymbolAddress((void**)&Kh,  g_Kh);
    cudaGetSymbolAddress((void**)&Vt,  g_Vt);
    cudaGetSymbolAddress((void**)&Ch,  g_Ch);

    cudaFuncSetAttribute(gemm_h<true>,
                         cudaFuncAttributeMaxDynamicSharedMemorySize, GEMM_SMEM);
    cudaFuncSetAttribute(gemm_h<false>,
                         cudaFuncAttributeMaxDynamicSharedMemorySize, GEMM_SMEM);
    cudaFuncSetAttribute(attn_h,
                         cudaFuncAttributeMaxDynamicSharedMemorySize, ATTN_SMEM);

    // prepass: fp16 conversions (+ weight transposes to [n][k])
    cvt_x<<<(M * D_IN) / 1024, 256>>>(x, Xh);
    transpose_h<<<dim3(64, 64), dim3(32, 8)>>>(Wq, WqT, 2048, 2048);
    transpose_h<<<dim3(16, 64), dim3(32, 8)>>>(Wk, WkT, 2048, 512);
    transpose_h<<<dim3(16, 64), dim3(32, 8)>>>(Wv, WvT, 2048, 512);
    transpose_h<<<dim3(64, 64), dim3(32, 8)>>>(Wo, WoT, 2048, 2048);

    // fused QKV projection: N = 2048 (Q) + 512 (K) + 512 (V^T) = 3072
    gemm_h<true><<<dim3(12, M / 128), 256, GEMM_SMEM>>>(
        Xh, WqT, WkT, WvT, Qh, Kh, Vt, nullptr, nullptr);

    attn_h<<<dim3(SEQ / 128, B * 16), 256, ATTN_SMEM>>>(Qh, Kh, Vt, Ch);

    // output projection + bias (fp32 out)
    gemm_h<false><<<dim3(8, M / 128), 256, GEMM_SMEM>>>(
        Ch, WoT, nullptr, nullptr, nullptr, nullptr, nullptr, (float*)d_out, bo);
}

// round 10
// speedup vs baseline: 2.2514x; 1.0084x over previous
#include <cuda_runtime.h>
#include <cuda_fp16.h>
#include <math_constants.h>
#include <cstdint>

#define D_IN   2048
#define D_OUT  2048
#define HD     128
#define NG     4
#define HPG    4
#define SEQ    2048
#define GK     2048      /* K dim of every GEMM */

// ---------------- scratch (no cudaMalloc allowed) ----------------
__device__ __half g_Xh [4096 * 2048];   // x, fp16
__device__ __half g_WqT[2048 * 2048];   // Wq^T [n][k] fp16
__device__ __half g_WkT[512  * 2048];
__device__ __half g_WvT[512  * 2048];
__device__ __half g_WoT[2048 * 2048];
__device__ __half g_Qh [4096 * 2048];   // q proj, scaled, fp16 [seq][dim]
__device__ __half g_Kh [4096 * 512];    // k proj fp16 [seq][gdim]
__device__ __half g_Vt [8 * 128 * 2048];// v proj TRANSPOSED [b*g][dim][seq]
__device__ __half g_Ch [4096 * 2048];   // ctx fp16

// ---------------- helpers ----------------
__device__ __forceinline__ void mma_f16(float* d, const uint32_t* a, const uint32_t* b) {
    asm volatile(
        "mma.sync.aligned.m16n8k16.row.col.f32.f16.f16.f32 "
        "{%0,%1,%2,%3}, {%4,%5,%6,%7}, {%8,%9}, {%0,%1,%2,%3};"
        : "+f"(d[0]), "+f"(d[1]), "+f"(d[2]), "+f"(d[3])
        : "r"(a[0]), "r"(a[1]), "r"(a[2]), "r"(a[3]), "r"(b[0]), "r"(b[1]));
}
__device__ __forceinline__ uint32_t smem_u32(const void* p) {
    uint32_t a;
    asm("{ .reg .u64 t; cvta.to.shared.u64 t, %1; cvt.u32.u64 %0, t; }" : "=r"(a) : "l"(p));
    return a;
}
__device__ __forceinline__ uint32_t packh2(float x, float y) {
    __half2 h = __floats2half2_rn(x, y);
    return *(uint32_t*)&h;
}
#define LDSM_X4(r0, r1, r2, r3, addr) \
    asm volatile("ldmatrix.sync.aligned.m8n8.x4.shared.b16 {%0,%1,%2,%3}, [%4];" \
        : "=r"(r0), "=r"(r1), "=r"(r2), "=r"(r3) : "r"(addr))
#define CP_ASYNC16(dst, src) \
    asm volatile("cp.async.cg.shared.global [%0], [%1], 16;" :: "r"(dst), "l"(src) : "memory")
#define CP_COMMIT() asm volatile("cp.async.commit_group;" ::: "memory")
#define CP_WAIT0()  asm volatile("cp.async.wait_group 0;" ::: "memory")
#define CP_WAIT1()  asm volatile("cp.async.wait_group 1;" ::: "memory")

#define SCALE 0.08838834764831845f   /* 1/sqrt(128) */

// ---------------- prepass ----------------
__global__ void cvt_x(const float* __restrict__ in, __half* __restrict__ out) {
    size_t i = ((size_t)blockIdx.x * blockDim.x + threadIdx.x) * 4;
    float4 v = *(const float4*)(in + i);
    uint2 o;
    o.x = packh2(v.x, v.y);
    o.y = packh2(v.z, v.w);
    *(uint2*)(out + i) = o;
}

// W [K][N] fp32 -> Wt [N][K] fp16
__global__ void transpose_h(const float* __restrict__ W, __half* __restrict__ Wt,
                            int K, int N) {
    __shared__ float t[32][33];
    int x = blockIdx.x * 32 + threadIdx.x;   // n
    int y = blockIdx.y * 32 + threadIdx.y;   // k
#pragma unroll
    for (int i = 0; i < 32; i += 8)
        t[threadIdx.y + i][threadIdx.x] = W[(size_t)(y + i) * N + x];
    __syncthreads();
    int x2 = blockIdx.y * 32 + threadIdx.x;  // k
    int y2 = blockIdx.x * 32 + threadIdx.y;  // n
#pragma unroll
    for (int i = 0; i < 32; i += 8)
        Wt[(size_t)(y2 + i) * K + x2] = __float2half_rn(t[threadIdx.x][threadIdx.y + i]);
}

// -- fp16 mma GEMM: CTA 128x128, 8 warps @ 32x64, BK=64, 3-stage, 2 CTA/SM --
#define GLDB 144                          /* smem row stride bytes (64h + pad) */
#define GAS_B (128 * GLDB)                /* 18432 B */
#define GSTG_B (2 * GAS_B)                /* 36864 B */
#define GEMM_SMEM (3 * GSTG_B)            /* 110592 B */

template <bool PROJ>
__global__ __launch_bounds__(256, 2) void gemm_h(
    const __half* __restrict__ A,
    const __half* __restrict__ B0, const __half* __restrict__ B1,
    const __half* __restrict__ B2,
    __half* __restrict__ Qo, __half* __restrict__ Ko, __half* __restrict__ Vo,
    float* __restrict__ Co, const float* __restrict__ bias)
{
    extern __shared__ char smc[];
    const int tid = threadIdx.x;
    const int wid = tid >> 5, l = tid & 31;
    const int lq = l >> 2, lr = l & 3;
    const int m0 = blockIdx.y * 128;
    const int n0 = blockIdx.x * 128;
    const int wm = (wid & 3) * 32, wn = (wid >> 2) * 64;
    const uint32_t smb = smem_u32(smc);

    const __half* Bp;
    if (PROJ) {
        if (n0 < 2048)      Bp = B0 + (size_t)n0 * GK;
        else if (n0 < 2560) Bp = B1 + (size_t)(n0 - 2048) * GK;
        else                Bp = B2 + (size_t)(n0 - 2560) * GK;
    } else Bp = B0 + (size_t)n0 * GK;

    float acc[2][8][4];
#pragma unroll
    for (int i = 0; i < 2; i++)
#pragma unroll
        for (int j = 0; j < 8; j++)
#pragma unroll
            for (int r = 0; r < 4; r++) acc[i][j][r] = 0.f;

    // ldmatrix lane-address components (144-B rows: 16r mod 128 -> conflict-free)
    const uint32_t a_lane = (uint32_t)((wm + (l & 15)) * GLDB + (l >> 4) * 16);
    const uint32_t b_lane = (uint32_t)((wn + (l & 7) + ((l >> 4) << 3)) * GLDB
                                       + ((l >> 3) & 1) * 16);

    // A tile 128x64: 1024 16B-chunks -> 4/thread; B same.
#define G_LOAD(s, kc) do {                                                        \
        uint32_t _ab = smb + (s) * GSTG_B;                                        \
        uint32_t _bb = _ab + GAS_B;                                               \
        _Pragma("unroll")                                                         \
        for (int _i = 0; _i < 4; _i++) {                                          \
            int _e = tid + _i * 256, _r = _e >> 3, _ch = _e & 7;                  \
            CP_ASYNC16(_ab + _r * GLDB + _ch * 16,                                \
                (const void*)(A + (size_t)(m0 + _r) * GK + (kc) * 64 + _ch * 8)); \
            CP_ASYNC16(_bb + _r * GLDB + _ch * 16,                                \
                (const void*)(Bp + (size_t)_r * GK + (kc) * 64 + _ch * 8));       \
        }                                                                         \
    } while (0)

    G_LOAD(0, 0); CP_COMMIT();
    G_LOAD(1, 1); CP_COMMIT();

    const int kiters = GK / 64;   // 32
    for (int it = 0; it < kiters; it++) {
        CP_WAIT1();
        __syncthreads();
        if (it + 2 < kiters) { G_LOAD((it + 2) % 3, it + 2); CP_COMMIT(); }

        const uint32_t abase = smb + (it % 3) * GSTG_B + a_lane;
        const uint32_t bbase = smb + (it % 3) * GSTG_B + GAS_B + b_lane;

#pragma unroll
        for (int ks = 0; ks < 4; ks++) {
            uint32_t af[2][4], bf[8][2];
#pragma unroll
            for (int mf = 0; mf < 2; mf++)
                LDSM_X4(af[mf][0], af[mf][1], af[mf][2], af[mf][3],
                        abase + mf * (16 * GLDB) + ks * 32);
#pragma unroll
            for (int p = 0; p < 4; p++)
                LDSM_X4(bf[2 * p][0], bf[2 * p][1], bf[2 * p + 1][0], bf[2 * p + 1][1],
                        bbase + p * (16 * GLDB) + ks * 32);
#pragma unroll
            for (int mf = 0; mf < 2; mf++)
#pragma unroll
                for (int nf = 0; nf < 8; nf++)
                    mma_f16(acc[mf][nf], af[mf], bf[nf]);
        }
        __syncthreads();
    }

    // epilogue
#pragma unroll
    for (int mf = 0; mf < 2; mf++) {
        const int row = m0 + wm + mf * 16 + lq;
#pragma unroll
        for (int nf = 0; nf < 8; nf++) {
            const int col = wn + nf * 8 + 2 * lr;
            const float c0 = acc[mf][nf][0], c1 = acc[mf][nf][1];
            const float c2 = acc[mf][nf][2], c3 = acc[mf][nf][3];
            if (!PROJ) {
                float2 b = *(const float2*)(bias + n0 + col);
                *(float2*)(Co + (size_t)row * 2048 + n0 + col) =
                    make_float2(c0 + b.x, c1 + b.y);
                *(float2*)(Co + (size_t)(row + 8) * 2048 + n0 + col) =
                    make_float2(c2 + b.x, c3 + b.y);
            } else if (n0 < 2048) {
                *(uint32_t*)(Qo + (size_t)row * 2048 + n0 + col) =
                    packh2(c0 * SCALE, c1 * SCALE);
                *(uint32_t*)(Qo + (size_t)(row + 8) * 2048 + n0 + col) =
                    packh2(c2 * SCALE, c3 * SCALE);
            } else if (n0 < 2560) {
                const int kc = n0 - 2048 + col;
                *(uint32_t*)(Ko + (size_t)row * 512 + kc) = packh2(c0, c1);
                *(uint32_t*)(Ko + (size_t)(row + 8) * 512 + kc) = packh2(c2, c3);
            } else {
                const int vd = n0 - 2560 + col;
                const int gi = vd >> 7, d = vd & 127;
                const int bi = row >> 11, s = row & 2047;
                __half* vb = Vo + ((size_t)(bi * NG + gi) * 128 + d) * 2048;
                vb[s]            = __float2half_rn(c0);
                vb[2048 + s]     = __float2half_rn(c1);
                vb[s + 8]        = __float2half_rn(c2);
                vb[2048 + s + 8] = __float2half_rn(c3);
            }
        }
    }
#undef G_LOAD
}

// -------- fp16 mma flash-attention: split-softmax 4x2 warps, 128-key tiles --
#define HLD 136
#define QS_B (128 * 272)
#define KS_B (128 * 272)
#define VS_B (128 * 272)
#define ATTN_SMEM (QS_B + 2 * KS_B + 2 * VS_B)   /* 174080 B */

__global__ __launch_bounds__(256, 1) void attn_h(
    const __half* __restrict__ Q, const __half* __restrict__ K,
    const __half* __restrict__ VT, __half* __restrict__ C)
{
    extern __shared__ char smc[];
    const int tid = threadIdx.x;
    const int wid = tid >> 5, l = tid & 31;
    const int lq = l >> 2, lr = l & 3;
    const int wr = wid >> 1, wc = wid & 1;
    const int wq = wr * 32;
    const int koff = wc * 64;

    const int qc = gridDim.x - 1 - blockIdx.x;   // long CTAs first
    const int hh = blockIdx.y;
    const int bi = hh >> 4;
    const int gi = (hh >> 2) & 3;
    const int hi = hh & 3;
    const int qcol = (gi * HPG + hi) * HD;
    const int kcol = gi * HD;
    const size_t rowbase = (size_t)bi * SEQ;
    const int qbase = qc * 128;
    const uint32_t smb = smem_u32(smc);
    const __half* vtb = VT + (size_t)(bi * NG + gi) * 128 * 2048;

    const uint32_t qa_lane = (uint32_t)((wq + (l & 15)) * 272 + (l >> 4) * 16);
    const uint32_t kb_lane = (uint32_t)((koff + (l & 7) + ((l >> 4) << 3)) * 272
                                        + ((l >> 3) & 1) * 16);
    const uint32_t vb_lane = (uint32_t)(((l & 7) + ((l >> 4) << 3)) * 272
                                        + ((l >> 3) & 1) * 16 + koff * 2);

    // ---- Q tile [128 q][128 d] fp16 ----
#pragma unroll
    for (int u = 0; u < 8; u++) {
        int e = tid + u * 256, r = e >> 4, ch = e & 15;
        CP_ASYNC16(smb + r * 272 + ch * 16,
                   (const void*)(Q + (rowbase + qbase + r) * 2048 + qcol + ch * 8));
    }

    float o[2][16][4];
#pragma unroll
    for (int mf = 0; mf < 2; mf++)
#pragma unroll
        for (int i = 0; i < 16; i++)
#pragma unroll
            for (int r = 0; r < 4; r++) o[mf][i][r] = 0.f;
    float mm[2][2], ll[2][2];
#pragma unroll
    for (int mf = 0; mf < 2; mf++) {
        mm[mf][0] = -CUDART_INF_F; mm[mf][1] = -CUDART_INF_F;
        ll[mf][0] = 0.f; ll[mf][1] = 0.f;
    }

    const int jmax = qc;

#define KV_LOAD(ss, jj) do {                                                     \
        uint32_t _kb = smb + QS_B + (ss) * KS_B;                                  \
        uint32_t _vb = smb + QS_B + 2 * KS_B + (ss) * VS_B;                       \
        _Pragma("unroll")                                                         \
        for (int _u = 0; _u < 8; _u++) {                                          \
            int _e = tid + _u * 256, _r = _e >> 4, _ch = _e & 15;                 \
            CP_ASYNC16(_kb + _r * 272 + _ch * 16,                                 \
                (const void*)(K + (rowbase + (jj) * 128 + _r) * 512 + kcol + _ch * 8)); \
            CP_ASYNC16(_vb + _r * 272 + _ch * 16,                                 \
                (const void*)(vtb + (size_t)_r * 2048 + (jj) * 128 + _ch * 8));   \
        }                                                                         \
    } while (0)

    KV_LOAD(0, 0); CP_COMMIT();

    for (int j = 0; j <= jmax; j++) {
        CP_WAIT0();
        __syncthreads();
        if (j < jmax) { KV_LOAD((j + 1) & 1, j + 1); CP_COMMIT(); }

        const int st = j & 1;
        const uint32_t qsb = smb;
        const uint32_t ksb = smb + QS_B + st * KS_B;
        const uint32_t vsb = smb + QS_B + 2 * KS_B + st * VS_B;
        const int kb = j * 128 + koff;
        if (kb > qbase + wq + 31) continue;

        // ---- S = Q @ K^T : 32 q x 64 keys ----
        float s_[2][8][4];
#pragma unroll
        for (int mf = 0; mf < 2; mf++)
#pragma unroll
            for (int nf = 0; nf < 8; nf++)
#pragma unroll
                for (int r = 0; r < 4; r++) s_[mf][nf][r] = 0.f;

#pragma unroll
        for (int kf = 0; kf < 8; kf++) {
            uint32_t qa[2][4], kbf[8][2];
#pragma unroll
            for (int mf = 0; mf < 2; mf++)
                LDSM_X4(qa[mf][0], qa[mf][1], qa[mf][2], qa[mf][3],
                        qsb + qa_lane + mf * (16 * 272) + kf * 32);
#pragma unroll
            for (int p = 0; p < 4; p++)
                LDSM_X4(kbf[2 * p][0], kbf[2 * p][1], kbf[2 * p + 1][0], kbf[2 * p + 1][1],
                        ksb + kb_lane + p * (16 * 272) + kf * 32);
#pragma unroll
            for (int nf = 0; nf < 8; nf++) {
                mma_f16(s_[0][nf], qa[0], kbf[nf]);
                mma_f16(s_[1][nf], qa[1], kbf[nf]);
            }
        }

        // ---- per-warp softmax over its 64-key half ----
        const bool needmask = (kb + 63 > qbase + wq);
        uint32_t P2[2][4][4];
#pragma unroll
        for (int mf = 0; mf < 2; mf++) {
            const int gr0 = qbase + wq + mf * 16 + lq;
            const int gr1 = gr0 + 8;
            float mx0 = -CUDART_INF_F, mx1 = -CUDART_INF_F;
#pragma unroll
            for (int nf = 0; nf < 8; nf++) {
                if (needmask) {
                    const int c0 = kb + nf * 8 + 2 * lr;
                    if (c0 > gr0)     s_[mf][nf][0] = -CUDART_INF_F;
                    if (c0 + 1 > gr0) s_[mf][nf][1] = -CUDART_INF_F;
                    if (c0 > gr1)     s_[mf][nf][2] = -CUDART_INF_F;
                    if (c0 + 1 > gr1) s_[mf][nf][3] = -CUDART_INF_F;
                }
                mx0 = fmaxf(mx0, fmaxf(s_[mf][nf][0], s_[mf][nf][1]));
                mx1 = fmaxf(mx1, fmaxf(s_[mf][nf][2], s_[mf][nf][3]));
            }
#pragma unroll
            for (int msk = 1; msk < 4; msk <<= 1) {
                mx0 = fmaxf(mx0, __shfl_xor_sync(0xffffffffu, mx0, msk));
                mx1 = fmaxf(mx1, __shfl_xor_sync(0xffffffffu, mx1, msk));
            }
            const float nm0 = fmaxf(mm[mf][0], mx0);
            const float nm1 = fmaxf(mm[mf][1], mx1);
            const float al0 = __expf(mm[mf][0] - nm0);
            const float al1 = __expf(mm[mf][1] - nm1);
            mm[mf][0] = nm0; mm[mf][1] = nm1;

            float sm0 = 0.f, sm1 = 0.f;
#pragma unroll
            for (int nf = 0; nf < 8; nf++) {
                float p0 = __expf(s_[mf][nf][0] - nm0);
                float p1 = __expf(s_[mf][nf][1] - nm0);
                float p2 = __expf(s_[mf][nf][2] - nm1);
                float p3 = __expf(s_[mf][nf][3] - nm1);
                sm0 += p0 + p1; sm1 += p2 + p3;
                s_[mf][nf][0] = p0; s_[mf][nf][1] = p1;
                s_[mf][nf][2] = p2; s_[mf][nf][3] = p3;
            }
#pragma unroll
            for (int msk = 1; msk < 4; msk <<= 1) {
                sm0 += __shfl_xor_sync(0xffffffffu, sm0, msk);
                sm1 += __shfl_xor_sync(0xffffffffu, sm1, msk);
            }
            ll[mf][0] = ll[mf][0] * al0 + sm0;
            ll[mf][1] = ll[mf][1] * al1 + sm1;
#pragma unroll
            for (int nf = 0; nf < 16; nf++) {
                o[mf][nf][0] *= al0; o[mf][nf][1] *= al0;
                o[mf][nf][2] *= al1; o[mf][nf][3] *= al1;
            }
#pragma unroll
            for (int kf = 0; kf < 4; kf++) {
                P2[mf][kf][0] = packh2(s_[mf][2 * kf][0],     s_[mf][2 * kf][1]);
                P2[mf][kf][1] = packh2(s_[mf][2 * kf][2],     s_[mf][2 * kf][3]);
                P2[mf][kf][2] = packh2(s_[mf][2 * kf + 1][0], s_[mf][2 * kf + 1][1]);
                P2[mf][kf][3] = packh2(s_[mf][2 * kf + 1][2], s_[mf][2 * kf + 1][3]);
            }
        }

        // ---- O += P @ V ----
#pragma unroll
        for (int kf = 0; kf < 4; kf++) {
            uint32_t vbf[16][2];
#pragma unroll
            for (int p = 0; p < 8; p++)
                LDSM_X4(vbf[2 * p][0], vbf[2 * p][1], vbf[2 * p + 1][0], vbf[2 * p + 1][1],
                        vsb + vb_lane + p * (16 * 272) + kf * 32);
#pragma unroll
            for (int nf = 0; nf < 16; nf++) {
                mma_f16(o[0][nf], P2[0][kf], vbf[nf]);
                mma_f16(o[1][nf], P2[1][kf], vbf[nf]);
            }
        }
    }

    // ---- merge key-halves: wc=1 publishes (fp32), wc=0 combines + stores ----
    float* Ox = (float*)smc;                 // [4][32][132] fp32
    float* St = Ox + 4 * 32 * 132;           // [128][2]
    __syncthreads();
    if (wc == 1) {
        float* ob = Ox + wr * 32 * 132;
#pragma unroll
        for (int mf = 0; mf < 2; mf++) {
            const int row0 = mf * 16 + lq;
#pragma unroll
            for (int nf = 0; nf < 16; nf++) {
                const int col = nf * 8 + 2 * lr;
                *(float2*)&ob[row0 * 132 + col]       = make_float2(o[mf][nf][0], o[mf][nf][1]);
                *(float2*)&ob[(row0 + 8) * 132 + col] = make_float2(o[mf][nf][2], o[mf][nf][3]);
            }
            if (lr == 0) {
                float* st = St + (wr * 32 + row0) * 2;
                st[0] = mm[mf][0]; st[1] = ll[mf][0];
                st[16] = mm[mf][1]; st[17] = ll[mf][1];
            }
        }
    }
    __syncthreads();
    if (wc == 0) {
        const float* ob = Ox + wr * 32 * 132;
#pragma unroll
        for (int mf = 0; mf < 2; mf++) {
            const int row0 = mf * 16 + lq;
            const float* st = St + (wr * 32 + row0) * 2;
            const float mo0 = st[0],  lo0 = st[1];
            const float mo1 = st[16], lo1 = st[17];
            const float M0 = fmaxf(mm[mf][0], mo0);
            const float M1 = fmaxf(mm[mf][1], mo1);
            const float as0 = __expf(mm[mf][0] - M0), ao0 = __expf(mo0 - M0);
            const float as1 = __expf(mm[mf][1] - M1), ao1 = __expf(mo1 - M1);
            const float inv0 = 1.f / (ll[mf][0] * as0 + lo0 * ao0);
            const float inv1 = 1.f / (ll[mf][1] * as1 + lo1 * ao1);
            const float fs0 = as0 * inv0, fo0 = ao0 * inv0;
            const float fs1 = as1 * inv1, fo1 = ao1 * inv1;
            const size_t r0 = rowbase + qbase + wq + row0;
            const size_t r1 = r0 + 8;
#pragma unroll
            for (int nf = 0; nf < 16; nf++) {
                const int col = nf * 8 + 2 * lr;
                float2 q0 = *(const float2*)&ob[row0 * 132 + col];
                float2 q1 = *(const float2*)&ob[(row0 + 8) * 132 + col];
                *(uint32_t*)(C + r0 * 2048 + qcol + col) =
                    packh2(o[mf][nf][0] * fs0 + q0.x * fo0,
                           o[mf][nf][1] * fs0 + q0.y * fo0);
                *(uint32_t*)(C + r1 * 2048 + qcol + col) =
                    packh2(o[mf][nf][2] * fs1 + q1.x * fo1,
                           o[mf][nf][3] * fs1 + q1.y * fo1);
            }
        }
    }
#undef KV_LOAD
}

// ---------------------------------------------------------------------------
extern "C" void kernel_launch(void* const* d_in, const int* in_sizes, int n_in,
                              void* d_out, int out_size)
{
    const float* x  = (const float*)d_in[0];
    const float* Wq = (const float*)d_in[1];
    const float* Wk = (const float*)d_in[2];
    const float* Wv = (const float*)d_in[3];
    const float* Wo = (const float*)d_in[4];
    const float* bo = (const float*)d_in[5];

    const int M = in_sizes[0] / D_IN;   // 4096
    const int B = M / SEQ;              // 2

    __half *Xh, *WqT, *WkT, *WvT, *WoT, *Qh, *Kh, *Vt, *Ch;
    cudaGetSymbolAddress((void**)&Xh,  g_Xh);
    cudaGetSymbolAddress((void**)&WqT, g_WqT);
    cudaGetSymbolAddress((void**)&WkT, g_WkT);
    cudaGetSymbolAddress((void**)&WvT, g_WvT);
    cudaGetSymbolAddress((void**)&WoT, g_WoT);
    cudaGetSymbolAddress((void**)&Qh,  g_Qh);
    cudaGetSymbolAddress((void**)&Kh,  g_Kh);
    cudaGetSymbolAddress((void**)&Vt,  g_Vt);
    cudaGetSymbolAddress((void**)&Ch,  g_Ch);

    cudaFuncSetAttribute(gemm_h<true>,
                         cudaFuncAttributeMaxDynamicSharedMemorySize, GEMM_SMEM);
    cudaFuncSetAttribute(gemm_h<false>,
                         cudaFuncAttributeMaxDynamicSharedMemorySize, GEMM_SMEM);
    cudaFuncSetAttribute(attn_h,
                         cudaFuncAttributeMaxDynamicSharedMemorySize, ATTN_SMEM);

    // prepass: fp16 conversions (+ weight transposes to [n][k])
    cvt_x<<<(M * D_IN) / 1024, 256>>>(x, Xh);
    transpose_h<<<dim3(64, 64), dim3(32, 8)>>>(Wq, WqT, 2048, 2048);
    transpose_h<<<dim3(16, 64), dim3(32, 8)>>>(Wk, WkT, 2048, 512);
    transpose_h<<<dim3(16, 64), dim3(32, 8)>>>(Wv, WvT, 2048, 512);
    transpose_h<<<dim3(64, 64), dim3(32, 8)>>>(Wo, WoT, 2048, 2048);

    // fused QKV projection: N = 2048 (Q) + 512 (K) + 512 (V^T) = 3072
    gemm_h<true><<<dim3(24, M / 128), 256, GEMM_SMEM>>>(
        Xh, WqT, WkT, WvT, Qh, Kh, Vt, nullptr, nullptr);

    attn_h<<<dim3(SEQ / 128, B * 16), 256, ATTN_SMEM>>>(Qh, Kh, Vt, Ch);

    // output projection + bias (fp32 out)
    gemm_h<false><<<dim3(16, M / 128), 256, GEMM_SMEM>>>(
        Ch, WoT, nullptr, nullptr, nullptr, nullptr, nullptr, (float*)d_out, bo);
}